// round 2
// baseline (speedup 1.0000x reference)
#include <cuda_runtime.h>
#include <math.h>

#define NB  2
#define SEQ 2048
#define DM  1024
#define NH  16
#define DH  64

// ---------------- scratch (device globals; no allocation allowed) -------------
__device__ float g_q  [(size_t)NB*NH*SEQ*DH];   // [B,H,L,dh]
__device__ float g_kT [(size_t)NB*NH*DH*SEQ];   // [B,H,dh,L]  (K transposed)
__device__ float g_v  [(size_t)NB*NH*SEQ*DH];   // [B,H,L,dh]
__device__ float g_ctx[(size_t)NB*SEQ*DM];      // [B,L,D]
__device__ float g_pv [(size_t)NB*NH*SEQ];      // [B,H,L]

// ---------------- QKV GEMM: C[m,n] = sum_k x[m,k]*W[n,k] + b[n] ---------------
// 64x64 tile, BK=16, 256 threads, 4x4 microtile. Scatters into g_q/g_kT/g_v.
__global__ void __launch_bounds__(256) qkv_gemm_kernel(const float* __restrict__ X,
                                                       const float* __restrict__ W,
                                                       const float* __restrict__ Bias)
{
    __shared__ float As[16][68];
    __shared__ float Ws[16][68];
    const int tm = blockIdx.y * 64;
    const int tn = blockIdx.x * 64;
    const int t  = threadIdx.x;
    const int tr = t >> 4, tc = t & 15;
    const int lrow = t >> 2;
    const int lcol = (t & 3) << 2;
    float acc[4][4] = {};
    for (int k0 = 0; k0 < DM; k0 += 16) {
        float4 a = *(const float4*)(X + (size_t)(tm + lrow)*DM + k0 + lcol);
        float4 w = *(const float4*)(W + (size_t)(tn + lrow)*DM + k0 + lcol);
        As[lcol+0][lrow]=a.x; As[lcol+1][lrow]=a.y; As[lcol+2][lrow]=a.z; As[lcol+3][lrow]=a.w;
        Ws[lcol+0][lrow]=w.x; Ws[lcol+1][lrow]=w.y; Ws[lcol+2][lrow]=w.z; Ws[lcol+3][lrow]=w.w;
        __syncthreads();
        #pragma unroll
        for (int kk = 0; kk < 16; kk++) {
            float4 av = *(const float4*)&As[kk][tr<<2];
            float4 wv = *(const float4*)&Ws[kk][tc<<2];
            float aa[4] = {av.x, av.y, av.z, av.w};
            float ww[4] = {wv.x, wv.y, wv.z, wv.w};
            #pragma unroll
            for (int i = 0; i < 4; i++)
                #pragma unroll
                for (int j = 0; j < 4; j++)
                    acc[i][j] += aa[i]*ww[j];
        }
        __syncthreads();
    }
    const int which = tn >> 10;          // 0:q 1:k 2:v  (tile never straddles)
    const int h     = (tn >> 6) & (NH-1);
    #pragma unroll
    for (int i = 0; i < 4; i++) {
        int m = tm + (tr<<2) + i;
        int b = m >> 11, l = m & (SEQ-1);
        int bh = b*NH + h;
        #pragma unroll
        for (int j = 0; j < 4; j++) {
            int d = (tc<<2) + j;
            float v = acc[i][j] + Bias[tn + d];
            if (which == 0)
                g_q[((size_t)bh*SEQ + l)*DH + d] = v;
            else if (which == 1)
                g_kT[((size_t)bh*DH + d)*SEQ + l] = v;
            else
                g_v[((size_t)bh*SEQ + l)*DH + d] = v;
        }
    }
}

// ---------------- out projection GEMM: out = ctx @ W^T + b --------------------
__global__ void __launch_bounds__(256) out_gemm_kernel(const float* __restrict__ W,
                                                       const float* __restrict__ Bias,
                                                       float* __restrict__ Out)
{
    __shared__ float As[16][68];
    __shared__ float Ws[16][68];
    const int tm = blockIdx.y * 64;
    const int tn = blockIdx.x * 64;
    const int t  = threadIdx.x;
    const int tr = t >> 4, tc = t & 15;
    const int lrow = t >> 2;
    const int lcol = (t & 3) << 2;
    float acc[4][4] = {};
    for (int k0 = 0; k0 < DM; k0 += 16) {
        float4 a = *(const float4*)(g_ctx + (size_t)(tm + lrow)*DM + k0 + lcol);
        float4 w = *(const float4*)(W     + (size_t)(tn + lrow)*DM + k0 + lcol);
        As[lcol+0][lrow]=a.x; As[lcol+1][lrow]=a.y; As[lcol+2][lrow]=a.z; As[lcol+3][lrow]=a.w;
        Ws[lcol+0][lrow]=w.x; Ws[lcol+1][lrow]=w.y; Ws[lcol+2][lrow]=w.z; Ws[lcol+3][lrow]=w.w;
        __syncthreads();
        #pragma unroll
        for (int kk = 0; kk < 16; kk++) {
            float4 av = *(const float4*)&As[kk][tr<<2];
            float4 wv = *(const float4*)&Ws[kk][tc<<2];
            float aa[4] = {av.x, av.y, av.z, av.w};
            float ww[4] = {wv.x, wv.y, wv.z, wv.w};
            #pragma unroll
            for (int i = 0; i < 4; i++)
                #pragma unroll
                for (int j = 0; j < 4; j++)
                    acc[i][j] += aa[i]*ww[j];
        }
        __syncthreads();
    }
    #pragma unroll
    for (int i = 0; i < 4; i++) {
        int m = tm + (tr<<2) + i;
        #pragma unroll
        for (int j = 0; j < 4; j++) {
            int n = tn + (tc<<2) + j;
            Out[(size_t)m*DM + n] = acc[i][j] + Bias[n];
        }
    }
}

// ---------------- phase projection: pv[b,h,l] = tanh(ps*(x·pw[h] + pb[h])) ----
__global__ void __launch_bounds__(128) phase_kernel(const float* __restrict__ X,
                                                    const float* __restrict__ PW,
                                                    const float* __restrict__ PB,
                                                    const float* __restrict__ pscale)
{
    __shared__ float xs[DM];
    const int row = blockIdx.x;            // b*L + l
    for (int i = threadIdx.x; i < DM; i += 128) xs[i] = X[(size_t)row*DM + i];
    __syncthreads();
    const int h  = threadIdx.x >> 3;
    const int ln = threadIdx.x & 7;
    float s = 0.f;
    for (int k = ln; k < DM; k += 8) s += xs[k]*PW[(size_t)h*DM + k];
    #pragma unroll
    for (int off = 4; off; off >>= 1) s += __shfl_xor_sync(0xffffffffu, s, off);
    if (ln == 0) {
        float v = tanhf(pscale[0]*(s + PB[h]));
        int b = row >> 11, l = row & (SEQ-1);
        g_pv[((size_t)(b*NH + h))*SEQ + l] = v;
    }
}

// ---------------- fused attention -------------------------------------------
// Block = (b, h, 16 q-rows). Full score row kept in smem, one-pass softmax,
// attn written once, P@V accumulated with 4-way key-set split.
#define QT  16
#define SST 2056            // padded row stride of score buffer
#define KC  256             // key chunk

static const size_t ATTN_SMEM_FLOATS =
    (size_t)QT*SST + 17408 + (size_t)QT*68 + 16 + SEQ + 16;

__global__ void __launch_bounds__(256) attn_kernel(float* __restrict__ attn_out,
                                                   const float* __restrict__ rscale_p)
{
    extern __shared__ float sm[];
    float* sc  = sm;                         // [QT][SST] score/exp rows
    float* kvb = sc  + (size_t)QT*SST;       // 17408 floats: K^T / V chunk / partials
    float* qs  = kvb + 17408;                // [QT][68]
    float* pq  = qs  + (size_t)QT*68;        // [16]
    float* pk  = pq  + 16;                   // [SEQ]
    float* red = pk  + SEQ;                  // [16]  (1/rowsum)

    const int qt = blockIdx.x, h = blockIdx.y, b = blockIdx.z;
    const int bh = b*NH + h;
    const float* Q  = g_q  + (size_t)bh*SEQ*DH;
    const float* KT = g_kT + (size_t)bh*DH*SEQ;
    const float* V  = g_v  + (size_t)bh*SEQ*DH;
    const float* PV = g_pv + (size_t)bh*SEQ;
    const int t = threadIdx.x;
    const float rs = rscale_p[0];

    // load Q tile, pre-scaled by 1/sqrt(dh)=1/8
    {
        int qr = t >> 4, c4 = (t & 15) << 2;
        float4 qv = *(const float4*)(Q + (size_t)(qt*QT + qr)*DH + c4);
        float* d = qs + qr*68 + c4;
        d[0]=qv.x*0.125f; d[1]=qv.y*0.125f; d[2]=qv.z*0.125f; d[3]=qv.w*0.125f;
    }
    if (t < QT) pq[t] = PV[qt*QT + t];
    for (int i = t; i < SEQ; i += 256) pk[i] = PV[i];

    const int rg = t >> 5;        // q-row group: rows {rg, rg+8}
    const int kg = t & 31;        // key lane: keys kg + 32*j

    // ---- scores + phase bias ----
    for (int kc = 0; kc < SEQ; kc += KC) {
        __syncthreads();
        #pragma unroll
        for (int f = t; f < 64*64; f += 256) {       // copy K^T chunk [64][256]
            int d = f >> 6, c4 = (f & 63) << 2;
            float4 kv = *(const float4*)(KT + (size_t)d*SEQ + kc + c4);
            *(float4*)(kvb + d*260 + c4) = kv;
        }
        __syncthreads();
        float acc0[8] = {}, acc1[8] = {};
        #pragma unroll 4
        for (int d = 0; d < DH; d++) {
            float q0 = qs[rg*68 + d];
            float q1 = qs[(rg+8)*68 + d];
            const float* kr = kvb + d*260 + kg;
            #pragma unroll
            for (int j = 0; j < 8; j++) {
                float kv = kr[32*j];
                acc0[j] += q0*kv;
                acc1[j] += q1*kv;
            }
        }
        float pq0 = pq[rg], pq1 = pq[rg+8];
        #pragma unroll
        for (int j = 0; j < 8; j++) {
            int c = kc + kg + 32*j;
            float ph = pk[c];
            float d0 = pq0 - ph, d1 = pq1 - ph;
            sc[rg*SST + c]     = acc0[j] - rs*d0*d0;
            sc[(rg+8)*SST + c] = acc1[j] - rs*d1*d1;
        }
    }
    __syncthreads();

    // ---- softmax (exp stored unnormalized; red[r] = 1/sum) ----
    {
        int r = t >> 4, c0 = t & 15;
        float m = -1e30f;
        for (int c = c0; c < SEQ; c += 16) m = fmaxf(m, sc[r*SST + c]);
        #pragma unroll
        for (int off = 8; off; off >>= 1) m = fmaxf(m, __shfl_xor_sync(0xffffffffu, m, off));
        float s = 0.f;
        for (int c = c0; c < SEQ; c += 16) {
            float e = __expf(sc[r*SST + c] - m);
            sc[r*SST + c] = e;
            s += e;
        }
        #pragma unroll
        for (int off = 8; off; off >>= 1) s += __shfl_xor_sync(0xffffffffu, s, off);
        if (c0 == 0) red[r] = 1.f / s;
    }
    __syncthreads();

    // ---- write normalized attention weights ----
    for (int r = 0; r < QT; r++) {
        float f = red[r];
        float* dst = attn_out + ((size_t)bh*SEQ + (size_t)qt*QT + r)*SEQ;
        for (int c = t; c < SEQ; c += 256)
            dst[c] = sc[r*SST + c]*f;
    }

    // ---- P @ V (4 key-sets, reduce at end) ----
    const int ts  = t >> 6;         // key set 0..3
    const int rg4 = (t >> 4) & 3;   // row group: rows rg4*4 .. +3
    const int dg  = t & 15;         // d group: dh cols dg*4 .. +3
    float acc[4][4] = {};
    for (int kc = 0; kc < SEQ; kc += KC) {
        __syncthreads();
        #pragma unroll
        for (int f = t; f < 64*64; f += 256) {       // copy V chunk [256][64]
            int key = f >> 4, d0 = (f & 15) << 2;
            float4 vv = *(const float4*)(V + (size_t)(kc + key)*DH + d0);
            *(float4*)(kvb + key*68 + d0) = vv;
        }
        __syncthreads();
        #pragma unroll 2
        for (int kk = ts*64; kk < ts*64 + 64; kk++) {
            float4 vv = *(const float4*)(kvb + kk*68 + (dg<<2));
            #pragma unroll
            for (int i = 0; i < 4; i++) {
                float p = sc[(rg4*4 + i)*SST + kc + kk];
                acc[i][0] += p*vv.x; acc[i][1] += p*vv.y;
                acc[i][2] += p*vv.z; acc[i][3] += p*vv.w;
            }
        }
    }
    __syncthreads();
    {   // reduce 4 partial sets via smem, scale by 1/rowsum, write ctx [B,L,D]
        float* part = kvb;                            // 4*16*64 floats
        #pragma unroll
        for (int i = 0; i < 4; i++)
            *(float4*)(part + ((size_t)(ts*16 + rg4*4 + i))*64 + (dg<<2)) =
                make_float4(acc[i][0], acc[i][1], acc[i][2], acc[i][3]);
        __syncthreads();
        int r = t >> 4, d0 = (t & 15) << 2;
        float4 s0 = *(const float4*)(part + (size_t)(0*16 + r)*64 + d0);
        float4 s1 = *(const float4*)(part + (size_t)(1*16 + r)*64 + d0);
        float4 s2 = *(const float4*)(part + (size_t)(2*16 + r)*64 + d0);
        float4 s3 = *(const float4*)(part + (size_t)(3*16 + r)*64 + d0);
        float f = red[r];
        float4 o;
        o.x = (s0.x+s1.x+s2.x+s3.x)*f;
        o.y = (s0.y+s1.y+s2.y+s3.y)*f;
        o.z = (s0.z+s1.z+s2.z+s3.z)*f;
        o.w = (s0.w+s1.w+s2.w+s3.w)*f;
        *(float4*)(g_ctx + ((size_t)b*SEQ + (size_t)qt*QT + r)*DM + h*DH + d0) = o;
    }
}

// ---------------- launch ------------------------------------------------------
extern "C" void kernel_launch(void* const* d_in, const int* in_sizes, int n_in,
                              void* d_out, int out_size)
{
    const float* x       = (const float*)d_in[0];
    const float* qkv_w   = (const float*)d_in[1];
    const float* qkv_b   = (const float*)d_in[2];
    const float* out_w   = (const float*)d_in[3];
    const float* out_b   = (const float*)d_in[4];
    const float* phase_w = (const float*)d_in[5];
    const float* phase_b = (const float*)d_in[6];
    const float* rscale  = (const float*)d_in[7];
    const float* pscale  = (const float*)d_in[8];

    float* out  = (float*)d_out;                       // [B,L,D]
    float* attn = out + (size_t)NB*SEQ*DM;             // [B,H,L,L]

    size_t smem_bytes = ATTN_SMEM_FLOATS * sizeof(float);
    cudaFuncSetAttribute(attn_kernel, cudaFuncAttributeMaxDynamicSharedMemorySize,
                         (int)smem_bytes);

    qkv_gemm_kernel<<<dim3(3*DM/64, NB*SEQ/64), 256>>>(x, qkv_w, qkv_b);
    phase_kernel<<<dim3(NB*SEQ), 128>>>(x, phase_w, phase_b, pscale);
    attn_kernel<<<dim3(SEQ/QT, NH, NB), 256, smem_bytes>>>(attn, rscale);
    out_gemm_kernel<<<dim3(DM/64, NB*SEQ/64), 256>>>(out_w, out_b, out);
}

// round 3
// speedup vs baseline: 1.0047x; 1.0047x over previous
#include <cuda_runtime.h>
#include <math.h>

#define NB  2
#define SEQ 2048
#define DM  1024
#define NH  16
#define DH  64

// ---------------- scratch (device globals; no allocation allowed) -------------
__device__ float g_q  [(size_t)NB*NH*SEQ*DH];   // [B,H,L,dh]
__device__ float g_kT [(size_t)NB*NH*DH*SEQ];   // [B,H,dh,L]  (K transposed)
__device__ float g_v  [(size_t)NB*NH*SEQ*DH];   // [B,H,L,dh]
__device__ float g_ctx[(size_t)NB*SEQ*DM];      // [B,L,D]
__device__ float g_pv [(size_t)NB*NH*SEQ];      // [B,H,L]

// ---------------- QKV GEMM: C[m,n] = sum_k x[m,k]*W[n,k] + b[n] ---------------
// 64x64 tile, BK=16, 256 threads, 4x4 microtile. Scatters into g_q/g_kT/g_v.
__global__ void __launch_bounds__(256) qkv_gemm_kernel(const float* __restrict__ X,
                                                       const float* __restrict__ W,
                                                       const float* __restrict__ Bias)
{
    __shared__ float As[16][68];
    __shared__ float Ws[16][68];
    const int tm = blockIdx.y * 64;
    const int tn = blockIdx.x * 64;
    const int t  = threadIdx.x;
    const int tr = t >> 4, tc = t & 15;
    const int lrow = t >> 2;
    const int lcol = (t & 3) << 2;
    float acc[4][4] = {};
    for (int k0 = 0; k0 < DM; k0 += 16) {
        float4 a = *(const float4*)(X + (size_t)(tm + lrow)*DM + k0 + lcol);
        float4 w = *(const float4*)(W + (size_t)(tn + lrow)*DM + k0 + lcol);
        As[lcol+0][lrow]=a.x; As[lcol+1][lrow]=a.y; As[lcol+2][lrow]=a.z; As[lcol+3][lrow]=a.w;
        Ws[lcol+0][lrow]=w.x; Ws[lcol+1][lrow]=w.y; Ws[lcol+2][lrow]=w.z; Ws[lcol+3][lrow]=w.w;
        __syncthreads();
        #pragma unroll
        for (int kk = 0; kk < 16; kk++) {
            float4 av = *(const float4*)&As[kk][tr<<2];
            float4 wv = *(const float4*)&Ws[kk][tc<<2];
            float aa[4] = {av.x, av.y, av.z, av.w};
            float ww[4] = {wv.x, wv.y, wv.z, wv.w};
            #pragma unroll
            for (int i = 0; i < 4; i++)
                #pragma unroll
                for (int j = 0; j < 4; j++)
                    acc[i][j] += aa[i]*ww[j];
        }
        __syncthreads();
    }
    const int which = tn >> 10;          // 0:q 1:k 2:v  (tile never straddles)
    const int h     = (tn >> 6) & (NH-1);
    #pragma unroll
    for (int i = 0; i < 4; i++) {
        int m = tm + (tr<<2) + i;
        int b = m >> 11, l = m & (SEQ-1);
        int bh = b*NH + h;
        #pragma unroll
        for (int j = 0; j < 4; j++) {
            int d = (tc<<2) + j;
            float v = acc[i][j] + Bias[tn + d];
            if (which == 0)
                g_q[((size_t)bh*SEQ + l)*DH + d] = v;
            else if (which == 1)
                g_kT[((size_t)bh*DH + d)*SEQ + l] = v;
            else
                g_v[((size_t)bh*SEQ + l)*DH + d] = v;
        }
    }
}

// ---------------- out projection GEMM: out = ctx @ W^T + b --------------------
__global__ void __launch_bounds__(256) out_gemm_kernel(const float* __restrict__ W,
                                                       const float* __restrict__ Bias,
                                                       float* __restrict__ Out)
{
    __shared__ float As[16][68];
    __shared__ float Ws[16][68];
    const int tm = blockIdx.y * 64;
    const int tn = blockIdx.x * 64;
    const int t  = threadIdx.x;
    const int tr = t >> 4, tc = t & 15;
    const int lrow = t >> 2;
    const int lcol = (t & 3) << 2;
    float acc[4][4] = {};
    for (int k0 = 0; k0 < DM; k0 += 16) {
        float4 a = *(const float4*)(g_ctx + (size_t)(tm + lrow)*DM + k0 + lcol);
        float4 w = *(const float4*)(W     + (size_t)(tn + lrow)*DM + k0 + lcol);
        As[lcol+0][lrow]=a.x; As[lcol+1][lrow]=a.y; As[lcol+2][lrow]=a.z; As[lcol+3][lrow]=a.w;
        Ws[lcol+0][lrow]=w.x; Ws[lcol+1][lrow]=w.y; Ws[lcol+2][lrow]=w.z; Ws[lcol+3][lrow]=w.w;
        __syncthreads();
        #pragma unroll
        for (int kk = 0; kk < 16; kk++) {
            float4 av = *(const float4*)&As[kk][tr<<2];
            float4 wv = *(const float4*)&Ws[kk][tc<<2];
            float aa[4] = {av.x, av.y, av.z, av.w};
            float ww[4] = {wv.x, wv.y, wv.z, wv.w};
            #pragma unroll
            for (int i = 0; i < 4; i++)
                #pragma unroll
                for (int j = 0; j < 4; j++)
                    acc[i][j] += aa[i]*ww[j];
        }
        __syncthreads();
    }
    #pragma unroll
    for (int i = 0; i < 4; i++) {
        int m = tm + (tr<<2) + i;
        #pragma unroll
        for (int j = 0; j < 4; j++) {
            int n = tn + (tc<<2) + j;
            Out[(size_t)m*DM + n] = acc[i][j] + Bias[n];
        }
    }
}

// ---------------- phase projection: pv[b,h,l] = tanh(ps*(x·pw[h] + pb[h])) ----
__global__ void __launch_bounds__(128) phase_kernel(const float* __restrict__ X,
                                                    const float* __restrict__ PW,
                                                    const float* __restrict__ PB,
                                                    const float* __restrict__ pscale)
{
    __shared__ float xs[DM];
    const int row = blockIdx.x;            // b*L + l
    for (int i = threadIdx.x; i < DM; i += 128) xs[i] = X[(size_t)row*DM + i];
    __syncthreads();
    const int h  = threadIdx.x >> 3;
    const int ln = threadIdx.x & 7;
    float s = 0.f;
    for (int k = ln; k < DM; k += 8) s += xs[k]*PW[(size_t)h*DM + k];
    #pragma unroll
    for (int off = 4; off; off >>= 1) s += __shfl_xor_sync(0xffffffffu, s, off);
    if (ln == 0) {
        float v = tanhf(pscale[0]*(s + PB[h]));
        int b = row >> 11, l = row & (SEQ-1);
        g_pv[((size_t)(b*NH + h))*SEQ + l] = v;
    }
}

// ---------------- fused attention -------------------------------------------
// Block = (b, h, 16 q-rows). Full score row kept in smem, one-pass softmax,
// attn written once, P@V accumulated with 4-way key-set split.
#define QT  16
#define SST 2056            // padded row stride of score buffer
#define KC  256             // key chunk

static const size_t ATTN_SMEM_FLOATS =
    (size_t)QT*SST + 17408 + (size_t)QT*68 + 16 + SEQ + 16;

__global__ void __launch_bounds__(256) attn_kernel(float* __restrict__ attn_out,
                                                   const float* __restrict__ rscale_p)
{
    extern __shared__ float sm[];
    float* sc  = sm;                         // [QT][SST] score/exp rows
    float* kvb = sc  + (size_t)QT*SST;       // 17408 floats: K^T / V chunk / partials
    float* qs  = kvb + 17408;                // [QT][68]
    float* pq  = qs  + (size_t)QT*68;        // [16]
    float* pk  = pq  + 16;                   // [SEQ]
    float* red = pk  + SEQ;                  // [16]  (1/rowsum)

    const int qt = blockIdx.x, h = blockIdx.y, b = blockIdx.z;
    const int bh = b*NH + h;
    const float* Q  = g_q  + (size_t)bh*SEQ*DH;
    const float* KT = g_kT + (size_t)bh*DH*SEQ;
    const float* V  = g_v  + (size_t)bh*SEQ*DH;
    const float* PV = g_pv + (size_t)bh*SEQ;
    const int t = threadIdx.x;
    const float rs = rscale_p[0];

    // load Q tile, pre-scaled by 1/sqrt(dh)=1/8
    {
        int qr = t >> 4, c4 = (t & 15) << 2;
        float4 qv = *(const float4*)(Q + (size_t)(qt*QT + qr)*DH + c4);
        float* d = qs + qr*68 + c4;
        d[0]=qv.x*0.125f; d[1]=qv.y*0.125f; d[2]=qv.z*0.125f; d[3]=qv.w*0.125f;
    }
    if (t < QT) pq[t] = PV[qt*QT + t];
    for (int i = t; i < SEQ; i += 256) pk[i] = PV[i];

    const int rg = t >> 5;        // q-row group: rows {rg, rg+8}
    const int kg = t & 31;        // key lane: keys kg + 32*j

    // ---- scores + phase bias ----
    for (int kc = 0; kc < SEQ; kc += KC) {
        __syncthreads();
        #pragma unroll
        for (int f = t; f < 64*64; f += 256) {       // copy K^T chunk [64][256]
            int d = f >> 6, c4 = (f & 63) << 2;
            float4 kv = *(const float4*)(KT + (size_t)d*SEQ + kc + c4);
            *(float4*)(kvb + d*260 + c4) = kv;
        }
        __syncthreads();
        float acc0[8] = {}, acc1[8] = {};
        #pragma unroll 4
        for (int d = 0; d < DH; d++) {
            float q0 = qs[rg*68 + d];
            float q1 = qs[(rg+8)*68 + d];
            const float* kr = kvb + d*260 + kg;
            #pragma unroll
            for (int j = 0; j < 8; j++) {
                float kv = kr[32*j];
                acc0[j] += q0*kv;
                acc1[j] += q1*kv;
            }
        }
        float pq0 = pq[rg], pq1 = pq[rg+8];
        #pragma unroll
        for (int j = 0; j < 8; j++) {
            int c = kc + kg + 32*j;
            float ph = pk[c];
            float d0 = pq0 - ph, d1 = pq1 - ph;
            sc[rg*SST + c]     = acc0[j] - rs*d0*d0;
            sc[(rg+8)*SST + c] = acc1[j] - rs*d1*d1;
        }
    }
    __syncthreads();

    // ---- softmax (exp stored unnormalized; red[r] = 1/sum) ----
    {
        int r = t >> 4, c0 = t & 15;
        float m = -1e30f;
        for (int c = c0; c < SEQ; c += 16) m = fmaxf(m, sc[r*SST + c]);
        #pragma unroll
        for (int off = 8; off; off >>= 1) m = fmaxf(m, __shfl_xor_sync(0xffffffffu, m, off));
        float s = 0.f;
        for (int c = c0; c < SEQ; c += 16) {
            float e = __expf(sc[r*SST + c] - m);
            sc[r*SST + c] = e;
            s += e;
        }
        #pragma unroll
        for (int off = 8; off; off >>= 1) s += __shfl_xor_sync(0xffffffffu, s, off);
        if (c0 == 0) red[r] = 1.f / s;
    }
    __syncthreads();

    // ---- write normalized attention weights ----
    for (int r = 0; r < QT; r++) {
        float f = red[r];
        float* dst = attn_out + ((size_t)bh*SEQ + (size_t)qt*QT + r)*SEQ;
        for (int c = t; c < SEQ; c += 256)
            dst[c] = sc[r*SST + c]*f;
    }

    // ---- P @ V (4 key-sets, reduce at end) ----
    const int ts  = t >> 6;         // key set 0..3
    const int rg4 = (t >> 4) & 3;   // row group: rows rg4*4 .. +3
    const int dg  = t & 15;         // d group: dh cols dg*4 .. +3
    float acc[4][4] = {};
    for (int kc = 0; kc < SEQ; kc += KC) {
        __syncthreads();
        #pragma unroll
        for (int f = t; f < 64*64; f += 256) {       // copy V chunk [256][64]
            int key = f >> 4, d0 = (f & 15) << 2;
            float4 vv = *(const float4*)(V + (size_t)(kc + key)*DH + d0);
            *(float4*)(kvb + key*68 + d0) = vv;
        }
        __syncthreads();
        #pragma unroll 2
        for (int kk = ts*64; kk < ts*64 + 64; kk++) {
            float4 vv = *(const float4*)(kvb + kk*68 + (dg<<2));
            #pragma unroll
            for (int i = 0; i < 4; i++) {
                float p = sc[(rg4*4 + i)*SST + kc + kk];
                acc[i][0] += p*vv.x; acc[i][1] += p*vv.y;
                acc[i][2] += p*vv.z; acc[i][3] += p*vv.w;
            }
        }
    }
    __syncthreads();
    {   // reduce 4 partial sets via smem, scale by 1/rowsum, write ctx [B,L,D]
        float* part = kvb;                            // 4*16*64 floats
        #pragma unroll
        for (int i = 0; i < 4; i++)
            *(float4*)(part + ((size_t)(ts*16 + rg4*4 + i))*64 + (dg<<2)) =
                make_float4(acc[i][0], acc[i][1], acc[i][2], acc[i][3]);
        __syncthreads();
        int r = t >> 4, d0 = (t & 15) << 2;
        float4 s0 = *(const float4*)(part + (size_t)(0*16 + r)*64 + d0);
        float4 s1 = *(const float4*)(part + (size_t)(1*16 + r)*64 + d0);
        float4 s2 = *(const float4*)(part + (size_t)(2*16 + r)*64 + d0);
        float4 s3 = *(const float4*)(part + (size_t)(3*16 + r)*64 + d0);
        float f = red[r];
        float4 o;
        o.x = (s0.x+s1.x+s2.x+s3.x)*f;
        o.y = (s0.y+s1.y+s2.y+s3.y)*f;
        o.z = (s0.z+s1.z+s2.z+s3.z)*f;
        o.w = (s0.w+s1.w+s2.w+s3.w)*f;
        *(float4*)(g_ctx + ((size_t)b*SEQ + (size_t)qt*QT + r)*DM + h*DH + d0) = o;
    }
}

// ---------------- launch ------------------------------------------------------
extern "C" void kernel_launch(void* const* d_in, const int* in_sizes, int n_in,
                              void* d_out, int out_size)
{
    const float* x       = (const float*)d_in[0];
    const float* qkv_w   = (const float*)d_in[1];
    const float* qkv_b   = (const float*)d_in[2];
    const float* out_w   = (const float*)d_in[3];
    const float* out_b   = (const float*)d_in[4];
    const float* phase_w = (const float*)d_in[5];
    const float* phase_b = (const float*)d_in[6];
    const float* rscale  = (const float*)d_in[7];
    const float* pscale  = (const float*)d_in[8];

    float* out  = (float*)d_out;                       // [B,L,D]
    float* attn = out + (size_t)NB*SEQ*DM;             // [B,H,L,L]

    size_t smem_bytes = ATTN_SMEM_FLOATS * sizeof(float);
    cudaFuncSetAttribute(attn_kernel, cudaFuncAttributeMaxDynamicSharedMemorySize,
                         (int)smem_bytes);

    qkv_gemm_kernel<<<dim3(3*DM/64, NB*SEQ/64), 256>>>(x, qkv_w, qkv_b);
    phase_kernel<<<dim3(NB*SEQ), 128>>>(x, phase_w, phase_b, pscale);
    attn_kernel<<<dim3(SEQ/QT, NH, NB), 256, smem_bytes>>>(attn, rscale);
    out_gemm_kernel<<<dim3(DM/64, NB*SEQ/64), 256>>>(out_w, out_b, out);
}

// round 7
// speedup vs baseline: 2.9266x; 2.9129x over previous
#include <cuda_runtime.h>
#include <cuda_bf16.h>
#include <math.h>
#include <stdint.h>

#define NB  2
#define SEQ 2048
#define DM  1024
#define NH  16
#define DH  64
#define MTOT (NB*SEQ)   // 4096

// ---------------- scratch (device globals; no allocation allowed) -------------
__device__ __nv_bfloat16 g_xh [(size_t)MTOT*DM],  g_xl [(size_t)MTOT*DM];
__device__ __nv_bfloat16 g_wqh[(size_t)3*DM*DM],  g_wql[(size_t)3*DM*DM];
__device__ __nv_bfloat16 g_woh[(size_t)DM*DM],    g_wol[(size_t)DM*DM];
__device__ __nv_bfloat16 g_qh [(size_t)NB*NH*SEQ*DH], g_ql[(size_t)NB*NH*SEQ*DH];
__device__ __nv_bfloat16 g_kh [(size_t)NB*NH*SEQ*DH], g_kl[(size_t)NB*NH*SEQ*DH];
__device__ __nv_bfloat16 g_vth[(size_t)NB*NH*DH*SEQ], g_vtl[(size_t)NB*NH*DH*SEQ];
__device__ __nv_bfloat16 g_ctxh[(size_t)MTOT*DM], g_ctxl[(size_t)MTOT*DM];
__device__ float g_pv[(size_t)NB*NH*SEQ];

// ======================= helpers ==============================================
__device__ __forceinline__ unsigned smem_u32(const void* p) {
    unsigned a;
    asm("{ .reg .u64 t; cvta.to.shared.u64 t, %1; cvt.u32.u64 %0, t; }" : "=r"(a) : "l"(p));
    return a;
}
__device__ __forceinline__ void ldsm4(unsigned addr, uint32_t r[4]) {
    asm volatile("ldmatrix.sync.aligned.m8n8.x4.shared.b16 {%0,%1,%2,%3}, [%4];"
        : "=r"(r[0]), "=r"(r[1]), "=r"(r[2]), "=r"(r[3]) : "r"(addr));
}
__device__ __forceinline__ void mmabf(float d[4], const uint32_t a[4], const uint32_t b[2]) {
    asm volatile("mma.sync.aligned.m16n8k16.row.col.f32.bf16.bf16.f32 "
        "{%0,%1,%2,%3},{%4,%5,%6,%7},{%8,%9},{%0,%1,%2,%3};"
        : "+f"(d[0]), "+f"(d[1]), "+f"(d[2]), "+f"(d[3])
        : "r"(a[0]), "r"(a[1]), "r"(a[2]), "r"(a[3]), "r"(b[0]), "r"(b[1]));
}
__device__ __forceinline__ void split_hl(float v, __nv_bfloat16& h, __nv_bfloat16& l) {
    h = __float2bfloat16(v);
    l = __float2bfloat16(v - __bfloat162float(h));
}

// ---------------- fp32 -> bf16 hi/lo conversion -------------------------------
__global__ void __launch_bounds__(256) cvt_kernel(const float* __restrict__ in,
                                                  __nv_bfloat16* __restrict__ oh,
                                                  __nv_bfloat16* __restrict__ ol, int n)
{
    for (int i = blockIdx.x*256 + threadIdx.x; i < n; i += gridDim.x*256) {
        __nv_bfloat16 h, l;
        split_hl(in[i], h, l);
        oh[i] = h; ol[i] = l;
    }
}

// ---------------- generic bf16x3 GEMM: C = A @ B^T + bias ---------------------
// A [4096][1024] hi/lo, B [N][1024] hi/lo. Block tile 128x128, 512 thr / 16 warps.
// MODE 0: write fp32 C (N=1024). MODE 1: scatter qkv into attention layouts.
#define GS_AH 0
#define GS_AL 18432
#define GS_BH 36864
#define GS_BL 55296
#define GEMM_SMEM 73728

template <int MODE>
__global__ void __launch_bounds__(512) gemm_kernel(const __nv_bfloat16* __restrict__ Ah,
                                                   const __nv_bfloat16* __restrict__ Al,
                                                   const __nv_bfloat16* __restrict__ Bh,
                                                   const __nv_bfloat16* __restrict__ Bl,
                                                   const float* __restrict__ bias,
                                                   float* __restrict__ Cout)
{
    extern __shared__ char smc[];
    const unsigned sb = smem_u32(smc);
    const int t = threadIdx.x, lane = t & 31, w = t >> 5;
    const int warpm = w >> 2, warpn = w & 3;
    const int blockM = blockIdx.y * 128, blockN = blockIdx.x * 128;
    const int gq = lane >> 2, tg = lane & 3;

    float acc[2][4][4] = {};

    for (int k0 = 0; k0 < DM; k0 += 64) {
        __syncthreads();
        #pragma unroll
        for (int p = 0; p < 2; p++) {
            int i = t + p*512;
            int row = i >> 3, c8 = (i & 7) << 3;
            unsigned so = (unsigned)(row*72 + c8)*2;
            size_t ga = (size_t)(blockM + row)*DM + k0 + c8;
            size_t gb = (size_t)(blockN + row)*DM + k0 + c8;
            *(uint4*)(smc + GS_AH + so) = *(const uint4*)(Ah + ga);
            *(uint4*)(smc + GS_AL + so) = *(const uint4*)(Al + ga);
            *(uint4*)(smc + GS_BH + so) = *(const uint4*)(Bh + gb);
            *(uint4*)(smc + GS_BL + so) = *(const uint4*)(Bl + gb);
        }
        __syncthreads();
        #pragma unroll
        for (int kp = 0; kp < 2; kp++) {
            uint32_t ah[2][2][4], al[2][2][4];
            #pragma unroll
            for (int mt = 0; mt < 2; mt++)
                #pragma unroll
                for (int j = 0; j < 2; j++) {
                    int ks = kp*2 + j;
                    unsigned arow = warpm*32 + mt*16 + (lane & 15);
                    unsigned aoff = arow*144 + ks*32 + (lane >> 4)*16;
                    ldsm4(sb + GS_AH + aoff, ah[mt][j]);
                    ldsm4(sb + GS_AL + aoff, al[mt][j]);
                }
            #pragma unroll
            for (int nt = 0; nt < 4; nt++) {
                unsigned brow = warpn*32 + nt*8 + (lane & 7);
                unsigned boff = brow*144 + kp*64 + (lane >> 3)*16;
                uint32_t bh[4], bl[4];
                ldsm4(sb + GS_BH + boff, bh);
                ldsm4(sb + GS_BL + boff, bl);
                #pragma unroll
                for (int j = 0; j < 2; j++) {
                    uint32_t bhj[2] = {bh[2*j], bh[2*j+1]};
                    uint32_t blj[2] = {bl[2*j], bl[2*j+1]};
                    #pragma unroll
                    for (int mt = 0; mt < 2; mt++) {
                        mmabf(acc[mt][nt], ah[mt][j], bhj);
                        mmabf(acc[mt][nt], ah[mt][j], blj);
                        mmabf(acc[mt][nt], al[mt][j], bhj);
                    }
                }
            }
        }
    }

    // epilogue
    #pragma unroll
    for (int mt = 0; mt < 2; mt++) {
        #pragma unroll
        for (int nt = 0; nt < 4; nt++) {
            int n  = blockN + warpn*32 + nt*8 + 2*tg;
            float b0 = bias[n], b1 = bias[n+1];
            int m0 = blockM + warpm*32 + mt*16 + gq;
            float v[2][2] = {{acc[mt][nt][0] + b0, acc[mt][nt][1] + b1},
                             {acc[mt][nt][2] + b0, acc[mt][nt][3] + b1}};
            #pragma unroll
            for (int r = 0; r < 2; r++) {
                int m = m0 + r*8;
                if (MODE == 0) {
                    float2 o; o.x = v[r][0]; o.y = v[r][1];
                    *(float2*)(Cout + (size_t)m*DM + n) = o;
                } else {
                    int which = n >> 10, hd = n & 1023;
                    int hh = hd >> 6, d = hd & 63;
                    int bb = m >> 11, l = m & (SEQ-1);
                    int bhid = bb*NH + hh;
                    float v0 = v[r][0], v1 = v[r][1];
                    if (which == 0) { v0 *= 0.125f; v1 *= 0.125f; }
                    __nv_bfloat16 h0, l0, h1, l1;
                    split_hl(v0, h0, l0); split_hl(v1, h1, l1);
                    if (which == 2) {
                        size_t base = ((size_t)bhid*DH + d)*SEQ + l;
                        g_vth[base] = h0; g_vth[base + SEQ] = h1;
                        g_vtl[base] = l0; g_vtl[base + SEQ] = l1;
                    } else {
                        size_t idx = ((size_t)bhid*SEQ + l)*DH + d;
                        __nv_bfloat16* H = which ? g_kh : g_qh;
                        __nv_bfloat16* L = which ? g_kl : g_ql;
                        __nv_bfloat162 hv; hv.x = h0; hv.y = h1;
                        __nv_bfloat162 lv; lv.x = l0; lv.y = l1;
                        *(__nv_bfloat162*)(H + idx) = hv;
                        *(__nv_bfloat162*)(L + idx) = lv;
                    }
                }
            }
        }
    }
}

// ---------------- phase projection --------------------------------------------
__global__ void __launch_bounds__(128) phase_kernel(const float* __restrict__ X,
                                                    const float* __restrict__ PW,
                                                    const float* __restrict__ PB,
                                                    const float* __restrict__ pscale)
{
    __shared__ float xs[DM];
    const int row = blockIdx.x;            // b*L + l
    for (int i = threadIdx.x; i < DM; i += 128) xs[i] = X[(size_t)row*DM + i];
    __syncthreads();
    const int h  = threadIdx.x >> 3;
    const int ln = threadIdx.x & 7;
    float s = 0.f;
    for (int k = ln; k < DM; k += 8) s += xs[k]*PW[(size_t)h*DM + k];
    #pragma unroll
    for (int off = 4; off; off >>= 1) s += __shfl_xor_sync(0xffffffffu, s, off);
    if (ln == 0) {
        float v = tanhf(pscale[0]*(s + PB[h]));
        int b = row >> 11, l = row & (SEQ-1);
        g_pv[((size_t)(b*NH + h))*SEQ + l] = v;
    }
}

// ---------------- fused attention (mma.sync, two-pass) ------------------------
#define AT_QH   0u
#define AT_QL   18432u
#define AT_KH   36864u
#define AT_KL   55296u
#define AT_VTH  73728u
#define AT_VTL  91136u
#define AT_PH   108544u
#define AT_PL   143360u
#define AT_PK   178176u
#define AT_PQ   186368u
#define AT_MS   186880u
#define AT_INV  187392u
#define AT_RED  187904u
#define ATTN_SMEM 189952u

__global__ void __launch_bounds__(512) attn_kernel(float* __restrict__ attn_out,
                                                   const float* __restrict__ rscale_p)
{
    extern __shared__ char smc[];
    const unsigned sb = smem_u32(smc);
    const int t = threadIdx.x, lane = t & 31, w = t >> 5;
    const int rg = w >> 1, R0 = rg*16;
    const int chalf = w & 1, C0 = chalf*64;
    const int gq = lane >> 2, tg = lane & 3;
    const int r1 = R0 + gq, r2 = r1 + 8;

    const int qt = blockIdx.x, h = blockIdx.y, b = blockIdx.z;
    const int bh = b*NH + h;
    const float rs = rscale_p[0];

    const __nv_bfloat16* Qh  = g_qh  + ((size_t)bh*SEQ + (size_t)qt*128)*DH;
    const __nv_bfloat16* Ql  = g_ql  + ((size_t)bh*SEQ + (size_t)qt*128)*DH;
    const __nv_bfloat16* Kh  = g_kh  + (size_t)bh*SEQ*DH;
    const __nv_bfloat16* Kl  = g_kl  + (size_t)bh*SEQ*DH;
    const __nv_bfloat16* VTh = g_vth + (size_t)bh*DH*SEQ;
    const __nv_bfloat16* VTl = g_vtl + (size_t)bh*DH*SEQ;
    const float*         PV  = g_pv  + (size_t)bh*SEQ;

    float* pkF  = (float*)(smc + AT_PK);
    float* pqF  = (float*)(smc + AT_PQ);
    float* mS   = (float*)(smc + AT_MS);
    float* invS = (float*)(smc + AT_INV);
    float* redM = (float*)(smc + AT_RED);       // [2][128]
    float* redS = redM + 256;                   // [2][128]

    // stage Q (hi/lo) + phase values
    #pragma unroll
    for (int p = 0; p < 2; p++) {
        int i = t + p*512;
        int row = i >> 3, c8 = (i & 7) << 3;
        unsigned so = (unsigned)(row*72 + c8)*2;
        *(uint4*)(smc + AT_QH + so) = *(const uint4*)(Qh + row*DH + c8);
        *(uint4*)(smc + AT_QL + so) = *(const uint4*)(Ql + row*DH + c8);
    }
    for (int i = t; i < SEQ; i += 512) pkF[i] = PV[i];
    if (t < 128) pqF[t] = PV[qt*128 + t];
    __syncthreads();

    // Q fragments (held in registers)
    uint32_t qh[4][4], ql[4][4];
    #pragma unroll
    for (int ks = 0; ks < 4; ks++) {
        unsigned arow = R0 + (lane & 15);
        unsigned aoff = arow*144 + ks*32 + (lane >> 4)*16;
        ldsm4(sb + AT_QH + aoff, qh[ks]);
        ldsm4(sb + AT_QL + aoff, ql[ks]);
    }

    const float pq1v = pqF[r1], pq2v = pqF[r2];

    // ================= PASS 1: row max + exp-sum ===============================
    float m1 = -1e30f, s1 = 0.f, m2 = -1e30f, s2 = 0.f;
    for (int ch = 0; ch < SEQ/128; ch++) {
        __syncthreads();
        const __nv_bfloat16* kh = Kh + (size_t)ch*128*DH;
        const __nv_bfloat16* kl = Kl + (size_t)ch*128*DH;
        #pragma unroll
        for (int p = 0; p < 2; p++) {
            int i = t + p*512;
            int row = i >> 3, c8 = (i & 7) << 3;
            unsigned so = (unsigned)(row*72 + c8)*2;
            *(uint4*)(smc + AT_KH + so) = *(const uint4*)(kh + row*DH + c8);
            *(uint4*)(smc + AT_KL + so) = *(const uint4*)(kl + row*DH + c8);
        }
        __syncthreads();

        float acc[8][4] = {};
        #pragma unroll
        for (int nt = 0; nt < 8; nt++) {
            unsigned brow = (unsigned)(C0 + 8*nt + (lane & 7));
            unsigned bbase = brow*144 + (lane >> 3)*16;
            #pragma unroll
            for (int kp = 0; kp < 2; kp++) {
                uint32_t bhv[4], blv[4];
                ldsm4(sb + AT_KH + bbase + kp*64, bhv);
                ldsm4(sb + AT_KL + bbase + kp*64, blv);
                #pragma unroll
                for (int j = 0; j < 2; j++) {
                    int ks = kp*2 + j;
                    uint32_t bhj[2] = {bhv[2*j], bhv[2*j+1]};
                    uint32_t blj[2] = {blv[2*j], blv[2*j+1]};
                    mmabf(acc[nt], qh[ks], bhj);
                    mmabf(acc[nt], qh[ks], blj);
                    mmabf(acc[nt], ql[ks], bhj);
                }
            }
        }

        // phase bias + online max/sum (two sweeps over acc to save registers)
        float mc1 = -1e30f, mc2 = -1e30f;
        #pragma unroll
        for (int nt = 0; nt < 8; nt++)
            #pragma unroll
            for (int e = 0; e < 2; e++) {
                int gc = ch*128 + C0 + 8*nt + 2*tg + e;
                float ph = pkF[gc];
                float d1 = pq1v - ph, d2 = pq2v - ph;
                mc1 = fmaxf(mc1, acc[nt][e]   - rs*d1*d1);
                mc2 = fmaxf(mc2, acc[nt][2+e] - rs*d2*d2);
            }
        float mn1 = fmaxf(m1, mc1), mn2 = fmaxf(m2, mc2);
        float a1 = 0.f, a2 = 0.f;
        #pragma unroll
        for (int nt = 0; nt < 8; nt++)
            #pragma unroll
            for (int e = 0; e < 2; e++) {
                int gc = ch*128 + C0 + 8*nt + 2*tg + e;
                float ph = pkF[gc];
                float d1 = pq1v - ph, d2 = pq2v - ph;
                a1 += __expf(acc[nt][e]   - rs*d1*d1 - mn1);
                a2 += __expf(acc[nt][2+e] - rs*d2*d2 - mn2);
            }
        s1 = s1*__expf(m1 - mn1) + a1; m1 = mn1;
        s2 = s2*__expf(m2 - mn2) + a2; m2 = mn2;
    }
    // reduce across tg lanes (butterfly merge)
    #pragma unroll
    for (int off = 1; off <= 2; off <<= 1) {
        float mo = __shfl_xor_sync(0xffffffffu, m1, off);
        float so = __shfl_xor_sync(0xffffffffu, s1, off);
        float mm = fmaxf(m1, mo);
        s1 = s1*__expf(m1 - mm) + so*__expf(mo - mm); m1 = mm;
        mo = __shfl_xor_sync(0xffffffffu, m2, off);
        so = __shfl_xor_sync(0xffffffffu, s2, off);
        mm = fmaxf(m2, mo);
        s2 = s2*__expf(m2 - mm) + so*__expf(mo - mm); m2 = mm;
    }
    if (tg == 0) {
        redM[chalf*128 + r1] = m1; redS[chalf*128 + r1] = s1;
        redM[chalf*128 + r2] = m2; redS[chalf*128 + r2] = s2;
    }
    __syncthreads();
    if (t < 128) {
        float ma = redM[t], mb = redM[128 + t];
        float sa = redS[t], sbv = redS[128 + t];
        float mm = fmaxf(ma, mb);
        float ss = sa*__expf(ma - mm) + sbv*__expf(mb - mm);
        mS[t] = mm; invS[t] = 1.f/ss;
    }
    __syncthreads();

    const float mr1 = mS[r1], i1 = invS[r1];
    const float mr2 = mS[r2], i2 = invS[r2];

    // ================= PASS 2: attn weights + P@V =============================
    float o[4][4] = {};
    for (int ch = 0; ch < SEQ/128; ch++) {
        __syncthreads();
        const __nv_bfloat16* kh = Kh + (size_t)ch*128*DH;
        const __nv_bfloat16* kl = Kl + (size_t)ch*128*DH;
        #pragma unroll
        for (int p = 0; p < 2; p++) {
            int i = t + p*512;
            int row = i >> 3, c8 = (i & 7) << 3;
            unsigned so = (unsigned)(row*72 + c8)*2;
            *(uint4*)(smc + AT_KH + so) = *(const uint4*)(kh + row*DH + c8);
            *(uint4*)(smc + AT_KL + so) = *(const uint4*)(kl + row*DH + c8);
        }
        #pragma unroll
        for (int p = 0; p < 2; p++) {
            int i = t + p*512;
            int dh = i >> 4, c8 = (i & 15) << 3;
            unsigned so = (unsigned)(dh*136 + c8)*2;
            *(uint4*)(smc + AT_VTH + so) = *(const uint4*)(VTh + (size_t)dh*SEQ + ch*128 + c8);
            *(uint4*)(smc + AT_VTL + so) = *(const uint4*)(VTl + (size_t)dh*SEQ + ch*128 + c8);
        }
        __syncthreads();

        float acc[8][4] = {};
        #pragma unroll
        for (int nt = 0; nt < 8; nt++) {
            unsigned brow = (unsigned)(C0 + 8*nt + (lane & 7));
            unsigned bbase = brow*144 + (lane >> 3)*16;
            #pragma unroll
            for (int kp = 0; kp < 2; kp++) {
                uint32_t bhv[4], blv[4];
                ldsm4(sb + AT_KH + bbase + kp*64, bhv);
                ldsm4(sb + AT_KL + bbase + kp*64, blv);
                #pragma unroll
                for (int j = 0; j < 2; j++) {
                    int ks = kp*2 + j;
                    uint32_t bhj[2] = {bhv[2*j], bhv[2*j+1]};
                    uint32_t blj[2] = {blv[2*j], blv[2*j+1]};
                    mmabf(acc[nt], qh[ks], bhj);
                    mmabf(acc[nt], qh[ks], blj);
                    mmabf(acc[nt], ql[ks], bhj);
                }
            }
        }

        // exp -> normalized P: write attn (global) + P hi/lo (smem)
        #pragma unroll
        for (int nt = 0; nt < 8; nt++) {
            int c0 = C0 + 8*nt + 2*tg;       // chunk-local col
            float ph0 = pkF[ch*128 + c0], ph1 = pkF[ch*128 + c0 + 1];
            float d10 = pq1v - ph0, d11 = pq1v - ph1;
            float d20 = pq2v - ph0, d21 = pq2v - ph1;
            float p10 = __expf(acc[nt][0] - rs*d10*d10 - mr1)*i1;
            float p11 = __expf(acc[nt][1] - rs*d11*d11 - mr1)*i1;
            float p20 = __expf(acc[nt][2] - rs*d20*d20 - mr2)*i2;
            float p21 = __expf(acc[nt][3] - rs*d21*d21 - mr2)*i2;
            float2 w1; w1.x = p10; w1.y = p11;
            float2 w2; w2.x = p20; w2.y = p21;
            *(float2*)(attn_out + ((size_t)bh*SEQ + (size_t)qt*128 + r1)*SEQ + ch*128 + c0) = w1;
            *(float2*)(attn_out + ((size_t)bh*SEQ + (size_t)qt*128 + r2)*SEQ + ch*128 + c0) = w2;
            __nv_bfloat16 h0, l0, h1_, l1_;
            split_hl(p10, h0, l0); split_hl(p11, h1_, l1_);
            __nv_bfloat162 hv, lv;
            hv.x = h0; hv.y = h1_; lv.x = l0; lv.y = l1_;
            *(__nv_bfloat162*)(smc + AT_PH + (unsigned)(r1*136 + c0)*2) = hv;
            *(__nv_bfloat162*)(smc + AT_PL + (unsigned)(r1*136 + c0)*2) = lv;
            split_hl(p20, h0, l0); split_hl(p21, h1_, l1_);
            hv.x = h0; hv.y = h1_; lv.x = l0; lv.y = l1_;
            *(__nv_bfloat162*)(smc + AT_PH + (unsigned)(r2*136 + c0)*2) = hv;
            *(__nv_bfloat162*)(smc + AT_PL + (unsigned)(r2*136 + c0)*2) = lv;
        }
        __syncthreads();

        // P @ V : k = 128 keys (8 ksteps)
        #pragma unroll
        for (int kp = 0; kp < 4; kp++) {
            uint32_t ph_[2][4], pl_[2][4];
            #pragma unroll
            for (int j = 0; j < 2; j++) {
                int ks = kp*2 + j;
                unsigned arow = R0 + (lane & 15);
                unsigned aoff = arow*272 + ks*32 + (lane >> 4)*16;
                ldsm4(sb + AT_PH + aoff, ph_[j]);
                ldsm4(sb + AT_PL + aoff, pl_[j]);
            }
            #pragma unroll
            for (int nt = 0; nt < 4; nt++) {
                unsigned brow = (unsigned)(32*chalf + 8*nt + (lane & 7));
                unsigned boff = brow*272 + kp*64 + (lane >> 3)*16;
                uint32_t bvh[4], bvl[4];
                ldsm4(sb + AT_VTH + boff, bvh);
                ldsm4(sb + AT_VTL + boff, bvl);
                #pragma unroll
                for (int j = 0; j < 2; j++) {
                    uint32_t bhj[2] = {bvh[2*j], bvh[2*j+1]};
                    uint32_t blj[2] = {bvl[2*j], bvl[2*j+1]};
                    mmabf(o[nt], ph_[j], bhj);
                    mmabf(o[nt], ph_[j], blj);
                    mmabf(o[nt], pl_[j], bhj);
                }
            }
        }
    }

    // ---- write ctx as bf16 hi/lo ----
    #pragma unroll
    for (int nt = 0; nt < 4; nt++) {
        int c = 32*chalf + 8*nt + 2*tg;
        #pragma unroll
        for (int r = 0; r < 2; r++) {
            int row = (r == 0) ? r1 : r2;
            float v0 = o[nt][2*r], v1 = o[nt][2*r + 1];
            __nv_bfloat16 h0, l0, h1_, l1_;
            split_hl(v0, h0, l0); split_hl(v1, h1_, l1_);
            size_t idx = ((size_t)b*SEQ + (size_t)qt*128 + row)*DM + h*DH + c;
            __nv_bfloat162 hv, lv;
            hv.x = h0; hv.y = h1_; lv.x = l0; lv.y = l1_;
            *(__nv_bfloat162*)(g_ctxh + idx) = hv;
            *(__nv_bfloat162*)(g_ctxl + idx) = lv;
        }
    }
}

// ---------------- launch ------------------------------------------------------
extern "C" void kernel_launch(void* const* d_in, const int* in_sizes, int n_in,
                              void* d_out, int out_size)
{
    const float* x       = (const float*)d_in[0];
    const float* qkv_w   = (const float*)d_in[1];
    const float* qkv_b   = (const float*)d_in[2];
    const float* out_w   = (const float*)d_in[3];
    const float* out_b   = (const float*)d_in[4];
    const float* phase_w = (const float*)d_in[5];
    const float* phase_b = (const float*)d_in[6];
    const float* rscale  = (const float*)d_in[7];
    const float* pscale  = (const float*)d_in[8];

    float* out  = (float*)d_out;                       // [B,L,D]
    float* attn = out + (size_t)NB*SEQ*DM;             // [B,H,L,L]

    static __nv_bfloat16 *xh_p = nullptr;
    __nv_bfloat16 *d_xh, *d_xl, *d_wqh, *d_wql, *d_woh, *d_wol;
    cudaGetSymbolAddress((void**)&d_xh,  g_xh);
    cudaGetSymbolAddress((void**)&d_xl,  g_xl);
    cudaGetSymbolAddress((void**)&d_wqh, g_wqh);
    cudaGetSymbolAddress((void**)&d_wql, g_wql);
    cudaGetSymbolAddress((void**)&d_woh, g_woh);
    cudaGetSymbolAddress((void**)&d_wol, g_wol);
    (void)xh_p;

    cudaFuncSetAttribute(gemm_kernel<0>, cudaFuncAttributeMaxDynamicSharedMemorySize, GEMM_SMEM);
    cudaFuncSetAttribute(gemm_kernel<1>, cudaFuncAttributeMaxDynamicSharedMemorySize, GEMM_SMEM);
    cudaFuncSetAttribute(attn_kernel, cudaFuncAttributeMaxDynamicSharedMemorySize, ATTN_SMEM);

    cvt_kernel<<<512, 256>>>(x,     d_xh,  d_xl,  MTOT*DM);
    cvt_kernel<<<512, 256>>>(qkv_w, d_wqh, d_wql, 3*DM*DM);
    cvt_kernel<<<512, 256>>>(out_w, d_woh, d_wol, DM*DM);

    gemm_kernel<1><<<dim3(3*DM/128, MTOT/128), 512, GEMM_SMEM>>>(
        d_xh, d_xl, d_wqh, d_wql, qkv_b, nullptr);
    phase_kernel<<<dim3(NB*SEQ), 128>>>(x, phase_w, phase_b, pscale);
    attn_kernel<<<dim3(SEQ/128, NH, NB), 512, ATTN_SMEM>>>(attn, rscale);

    __nv_bfloat16 *d_ctxh, *d_ctxl;
    cudaGetSymbolAddress((void**)&d_ctxh, g_ctxh);
    cudaGetSymbolAddress((void**)&d_ctxl, g_ctxl);
    gemm_kernel<0><<<dim3(DM/128, MTOT/128), 512, GEMM_SMEM>>>(
        d_ctxh, d_ctxl, d_woh, d_wol, out_b, out);
}

// round 9
// speedup vs baseline: 3.1859x; 1.0886x over previous
#include <cuda_runtime.h>
#include <cuda_bf16.h>
#include <math.h>
#include <stdint.h>

#define NB  2
#define SEQ 2048
#define DM  1024
#define NH  16
#define DH  64
#define MTOT (NB*SEQ)   // 4096
#define NCH (SEQ/128)   // 16

// ---------------- scratch (device globals; no allocation allowed) -------------
__device__ __nv_bfloat16 g_xh [(size_t)MTOT*DM],  g_xl [(size_t)MTOT*DM];
__device__ __nv_bfloat16 g_wqh[(size_t)3*DM*DM],  g_wql[(size_t)3*DM*DM];
__device__ __nv_bfloat16 g_woh[(size_t)DM*DM],    g_wol[(size_t)DM*DM];
__device__ __nv_bfloat16 g_qh [(size_t)NB*NH*SEQ*DH], g_ql[(size_t)NB*NH*SEQ*DH];
__device__ __nv_bfloat16 g_kh [(size_t)NB*NH*SEQ*DH], g_kl[(size_t)NB*NH*SEQ*DH];
__device__ __nv_bfloat16 g_vth[(size_t)NB*NH*DH*SEQ], g_vtl[(size_t)NB*NH*DH*SEQ];
__device__ __nv_bfloat16 g_ctxh[(size_t)MTOT*DM], g_ctxl[(size_t)MTOT*DM];
__device__ float g_pv[(size_t)NB*NH*SEQ];

// ======================= helpers ==============================================
__device__ __forceinline__ unsigned smem_u32(const void* p) {
    unsigned a;
    asm("{ .reg .u64 t; cvta.to.shared.u64 t, %1; cvt.u32.u64 %0, t; }" : "=r"(a) : "l"(p));
    return a;
}
__device__ __forceinline__ void ldsm4(unsigned addr, uint32_t r[4]) {
    asm volatile("ldmatrix.sync.aligned.m8n8.x4.shared.b16 {%0,%1,%2,%3}, [%4];"
        : "=r"(r[0]), "=r"(r[1]), "=r"(r[2]), "=r"(r[3]) : "r"(addr));
}
__device__ __forceinline__ void mmabf(float d[4], const uint32_t a[4], const uint32_t b[2]) {
    asm volatile("mma.sync.aligned.m16n8k16.row.col.f32.bf16.bf16.f32 "
        "{%0,%1,%2,%3},{%4,%5,%6,%7},{%8,%9},{%0,%1,%2,%3};"
        : "+f"(d[0]), "+f"(d[1]), "+f"(d[2]), "+f"(d[3])
        : "r"(a[0]), "r"(a[1]), "r"(a[2]), "r"(a[3]), "r"(b[0]), "r"(b[1]));
}
__device__ __forceinline__ void split_hl(float v, __nv_bfloat16& h, __nv_bfloat16& l) {
    h = __float2bfloat16(v);
    l = __float2bfloat16(v - __bfloat162float(h));
}
__device__ __forceinline__ uint32_t pack_hl_hi(float a, float b) {
    __nv_bfloat162 hv; hv.x = __float2bfloat16(a); hv.y = __float2bfloat16(b);
    return *(uint32_t*)&hv;
}
__device__ __forceinline__ uint32_t pack_hl_lo(float a, float b) {
    __nv_bfloat16 ha = __float2bfloat16(a), hb = __float2bfloat16(b);
    __nv_bfloat162 lv;
    lv.x = __float2bfloat16(a - __bfloat162float(ha));
    lv.y = __float2bfloat16(b - __bfloat162float(hb));
    return *(uint32_t*)&lv;
}
__device__ __forceinline__ void cp16(unsigned saddr, const void* gaddr) {
    asm volatile("cp.async.cg.shared.global [%0], [%1], 16;" :: "r"(saddr), "l"(gaddr));
}
#define CP_COMMIT() asm volatile("cp.async.commit_group;" ::: "memory")
#define CP_WAIT(n)  asm volatile("cp.async.wait_group %0;" :: "n"(n) : "memory")

// ---------------- fp32 -> bf16 hi/lo conversion -------------------------------
__global__ void __launch_bounds__(256) cvt_kernel(const float* __restrict__ in,
                                                  __nv_bfloat16* __restrict__ oh,
                                                  __nv_bfloat16* __restrict__ ol, int n)
{
    for (int i = blockIdx.x*256 + threadIdx.x; i < n; i += gridDim.x*256) {
        __nv_bfloat16 h, l;
        split_hl(in[i], h, l);
        oh[i] = h; ol[i] = l;
    }
}

// ---------------- generic bf16x3 GEMM: C = A @ B^T + bias ---------------------
// Block tile 128x128, 512 thr / 16 warps, 2-stage cp.async double buffering.
#define GS_AH 0u
#define GS_AL 18432u
#define GS_BH 36864u
#define GS_BL 55296u
#define GS_STAGE 73728u
#define GEMM_SMEM (2u*GS_STAGE)

template <int MODE>
__global__ void __launch_bounds__(512) gemm_kernel(const __nv_bfloat16* __restrict__ Ah,
                                                   const __nv_bfloat16* __restrict__ Al,
                                                   const __nv_bfloat16* __restrict__ Bh,
                                                   const __nv_bfloat16* __restrict__ Bl,
                                                   const float* __restrict__ bias,
                                                   float* __restrict__ Cout)
{
    extern __shared__ char smc[];
    const unsigned sb = smem_u32(smc);
    const int t = threadIdx.x, lane = t & 31, w = t >> 5;
    const int warpm = w >> 2, warpn = w & 3;
    const int blockM = blockIdx.y * 128, blockN = blockIdx.x * 128;
    const int gq = lane >> 2, tg = lane & 3;

    const int prow = t >> 3, pc8 = (t & 7) << 3;           // prefetch coords (1st half)
    const unsigned pso = (unsigned)(prow*72 + pc8)*2;

    float acc[2][4][4] = {};

    // prefetch k-tile kt into stage s
    auto prefetch = [&](int kt, int s) {
        unsigned st = sb + (unsigned)s*GS_STAGE;
        int k0 = kt*64;
        #pragma unroll
        for (int p = 0; p < 2; p++) {
            int row = prow + p*64;
            unsigned so = pso + (unsigned)p*64*144;
            size_t ga = (size_t)(blockM + row)*DM + k0 + pc8;
            size_t gb = (size_t)(blockN + row)*DM + k0 + pc8;
            cp16(st + GS_AH + so, Ah + ga);
            cp16(st + GS_AL + so, Al + ga);
            cp16(st + GS_BH + so, Bh + gb);
            cp16(st + GS_BL + so, Bl + gb);
        }
    };

    prefetch(0, 0); CP_COMMIT();

    for (int kt = 0; kt < 16; kt++) {
        if (kt + 1 < 16) { prefetch(kt+1, (kt+1)&1); CP_COMMIT(); CP_WAIT(1); }
        else CP_WAIT(0);
        __syncthreads();
        const unsigned st = sb + (unsigned)(kt & 1)*GS_STAGE;
        #pragma unroll
        for (int kp = 0; kp < 2; kp++) {
            uint32_t ah[2][2][4], al[2][2][4];
            #pragma unroll
            for (int mt = 0; mt < 2; mt++)
                #pragma unroll
                for (int j = 0; j < 2; j++) {
                    int ks = kp*2 + j;
                    unsigned arow = warpm*32 + mt*16 + (lane & 15);
                    unsigned aoff = arow*144 + ks*32 + (lane >> 4)*16;
                    ldsm4(st + GS_AH + aoff, ah[mt][j]);
                    ldsm4(st + GS_AL + aoff, al[mt][j]);
                }
            #pragma unroll
            for (int nt = 0; nt < 4; nt++) {
                unsigned brow = warpn*32 + nt*8 + (lane & 7);
                unsigned boff = brow*144 + kp*64 + (lane >> 3)*16;
                uint32_t bh[4], bl[4];
                ldsm4(st + GS_BH + boff, bh);
                ldsm4(st + GS_BL + boff, bl);
                #pragma unroll
                for (int j = 0; j < 2; j++) {
                    uint32_t bhj[2] = {bh[2*j], bh[2*j+1]};
                    uint32_t blj[2] = {bl[2*j], bl[2*j+1]};
                    #pragma unroll
                    for (int mt = 0; mt < 2; mt++) {
                        mmabf(acc[mt][nt], ah[mt][j], bhj);
                        mmabf(acc[mt][nt], ah[mt][j], blj);
                        mmabf(acc[mt][nt], al[mt][j], bhj);
                    }
                }
            }
        }
        __syncthreads();
    }

    // epilogue
    #pragma unroll
    for (int mt = 0; mt < 2; mt++) {
        #pragma unroll
        for (int nt = 0; nt < 4; nt++) {
            int n  = blockN + warpn*32 + nt*8 + 2*tg;
            float b0 = bias[n], b1 = bias[n+1];
            int m0 = blockM + warpm*32 + mt*16 + gq;
            float v[2][2] = {{acc[mt][nt][0] + b0, acc[mt][nt][1] + b1},
                             {acc[mt][nt][2] + b0, acc[mt][nt][3] + b1}};
            #pragma unroll
            for (int r = 0; r < 2; r++) {
                int m = m0 + r*8;
                if (MODE == 0) {
                    float2 o; o.x = v[r][0]; o.y = v[r][1];
                    *(float2*)(Cout + (size_t)m*DM + n) = o;
                } else {
                    int which = n >> 10, hd = n & 1023;
                    int hh = hd >> 6, d = hd & 63;
                    int bb = m >> 11, l = m & (SEQ-1);
                    int bhid = bb*NH + hh;
                    float v0 = v[r][0], v1 = v[r][1];
                    if (which == 0) { v0 *= 0.125f; v1 *= 0.125f; }
                    __nv_bfloat16 h0, l0, h1, l1;
                    split_hl(v0, h0, l0); split_hl(v1, h1, l1);
                    if (which == 2) {
                        size_t base = ((size_t)bhid*DH + d)*SEQ + l;
                        g_vth[base] = h0; g_vth[base + SEQ] = h1;
                        g_vtl[base] = l0; g_vtl[base + SEQ] = l1;
                    } else {
                        size_t idx = ((size_t)bhid*SEQ + l)*DH + d;
                        __nv_bfloat16* H = which ? g_kh : g_qh;
                        __nv_bfloat16* L = which ? g_kl : g_ql;
                        __nv_bfloat162 hv; hv.x = h0; hv.y = h1;
                        __nv_bfloat162 lv; lv.x = l0; lv.y = l1;
                        *(__nv_bfloat162*)(H + idx) = hv;
                        *(__nv_bfloat162*)(L + idx) = lv;
                    }
                }
            }
        }
    }
}

// ---------------- phase projection --------------------------------------------
__global__ void __launch_bounds__(128) phase_kernel(const float* __restrict__ X,
                                                    const float* __restrict__ PW,
                                                    const float* __restrict__ PB,
                                                    const float* __restrict__ pscale)
{
    __shared__ float xs[DM];
    const int row = blockIdx.x;            // b*L + l
    for (int i = threadIdx.x; i < DM; i += 128) xs[i] = X[(size_t)row*DM + i];
    __syncthreads();
    const int h  = threadIdx.x >> 3;
    const int ln = threadIdx.x & 7;
    float s = 0.f;
    for (int k = ln; k < DM; k += 8) s += xs[k]*PW[(size_t)h*DM + k];
    #pragma unroll
    for (int off = 4; off; off >>= 1) s += __shfl_xor_sync(0xffffffffu, s, off);
    if (ln == 0) {
        float v = tanhf(pscale[0]*(s + PB[h]));
        int b = row >> 11, l = row & (SEQ-1);
        g_pv[((size_t)(b*NH + h))*SEQ + l] = v;
    }
}

// ---------------- fused attention (mma.sync, 2-pass, register P) --------------
#define AT_Q(hl)    (18432u*(unsigned)(hl))
#define AT_K(s,hl)  (36864u  + 18432u*(unsigned)((s)*2+(hl)))
#define AT_V(s,hl)  (110592u + 17408u*(unsigned)((s)*2+(hl)))
#define AT_PK    180224u
#define AT_PK2   188416u
#define AT_PQ    196608u
#define AT_MS    197120u
#define AT_INV   197632u
#define AT_RED   198144u
#define AT_OPART 36864u          /* reuse K buffers post-loop */
#define ATTN_SMEM 200192u

__global__ void __launch_bounds__(512) attn_kernel(float* __restrict__ attn_out,
                                                   const float* __restrict__ rscale_p)
{
    extern __shared__ char smc[];
    const unsigned sb = smem_u32(smc);
    const int t = threadIdx.x, lane = t & 31, w = t >> 5;
    const int R0 = (w >> 1)*16;
    const int chalf = w & 1, C0 = chalf*64;
    const int gq = lane >> 2, tg = lane & 3;
    const int r1 = R0 + gq, r2 = r1 + 8;

    const int qt = blockIdx.x, h = blockIdx.y, b = blockIdx.z;
    const int bh = b*NH + h;
    const float rs = rscale_p[0];

    const __nv_bfloat16* Qh  = g_qh  + ((size_t)bh*SEQ + (size_t)qt*128)*DH;
    const __nv_bfloat16* Ql  = g_ql  + ((size_t)bh*SEQ + (size_t)qt*128)*DH;
    const __nv_bfloat16* Kh  = g_kh  + (size_t)bh*SEQ*DH;
    const __nv_bfloat16* Kl  = g_kl  + (size_t)bh*SEQ*DH;
    const __nv_bfloat16* VTh = g_vth + (size_t)bh*DH*SEQ;
    const __nv_bfloat16* VTl = g_vtl + (size_t)bh*DH*SEQ;
    const float*         PV  = g_pv  + (size_t)bh*SEQ;

    float* pkF  = (float*)(smc + AT_PK);
    float* pk2F = (float*)(smc + AT_PK2);
    float* pqF  = (float*)(smc + AT_PQ);
    float* mS   = (float*)(smc + AT_MS);
    float* invS = (float*)(smc + AT_INV);
    float* redM = (float*)(smc + AT_RED);       // [2][128]
    float* redS = redM + 256;                   // [2][128]

    const int krow = t >> 3, kc8 = (t & 7) << 3;
    const unsigned kso = (unsigned)(krow*72 + kc8)*2;
    const int vdh = t >> 4, vc8 = (t & 15) << 3;
    const unsigned vso = (unsigned)(vdh*136 + vc8)*2;

    auto prefetch_k = [&](int ch, int s) {
        const __nv_bfloat16* kh = Kh + (size_t)ch*128*DH;
        const __nv_bfloat16* kl = Kl + (size_t)ch*128*DH;
        #pragma unroll
        for (int p = 0; p < 2; p++) {
            int row = krow + p*64;
            unsigned so = kso + (unsigned)p*64*144;
            cp16(sb + AT_K(s,0) + so, kh + row*DH + kc8);
            cp16(sb + AT_K(s,1) + so, kl + row*DH + kc8);
        }
    };
    auto prefetch_v = [&](int ch, int s) {
        #pragma unroll
        for (int p = 0; p < 2; p++) {
            int dh = vdh + p*32;
            unsigned so = vso + (unsigned)p*32*272;
            cp16(sb + AT_V(s,0) + so, VTh + (size_t)dh*SEQ + ch*128 + vc8);
            cp16(sb + AT_V(s,1) + so, VTl + (size_t)dh*SEQ + ch*128 + vc8);
        }
    };

    // stage Q (hi/lo) + phase values
    prefetch_k(0, 0); CP_COMMIT();
    #pragma unroll
    for (int p = 0; p < 2; p++) {
        int i = t + p*512;
        int row = i >> 3, c8 = (i & 7) << 3;
        unsigned so = (unsigned)(row*72 + c8)*2;
        *(uint4*)(smc + AT_Q(0) + so) = *(const uint4*)(Qh + row*DH + c8);
        *(uint4*)(smc + AT_Q(1) + so) = *(const uint4*)(Ql + row*DH + c8);
    }
    for (int i = t; i < SEQ; i += 512) {
        float pv = PV[i];
        pkF[i] = pv; pk2F[i] = -rs*pv*pv;
    }
    if (t < 128) pqF[t] = PV[qt*128 + t];
    __syncthreads();

    // Q fragments (held in registers across both passes)
    uint32_t qh[4][4], ql[4][4];
    #pragma unroll
    for (int ks = 0; ks < 4; ks++) {
        unsigned arow = R0 + (lane & 15);
        unsigned aoff = arow*144 + ks*32 + (lane >> 4)*16;
        ldsm4(sb + AT_Q(0) + aoff, qh[ks]);
        ldsm4(sb + AT_Q(1) + aoff, ql[ks]);
    }

    const float pq1v = pqF[r1], pq2v = pqF[r2];
    const float a1r = 2.f*rs*pq1v, b1r = -rs*pq1v*pq1v;
    const float a2r = 2.f*rs*pq2v, b2r = -rs*pq2v*pq2v;

    // ================= PASS 1: row max + exp-sum ===============================
    float m1 = -1e30f, s1 = 0.f, m2 = -1e30f, s2 = 0.f;
    for (int ch = 0; ch < NCH; ch++) {
        if (ch + 1 < NCH) { prefetch_k(ch+1, (ch+1)&1); CP_COMMIT(); CP_WAIT(1); }
        else CP_WAIT(0);
        __syncthreads();
        const unsigned kbh = sb + AT_K(ch & 1, 0), kbl = sb + AT_K(ch & 1, 1);

        float acc[8][4] = {};
        #pragma unroll
        for (int nt = 0; nt < 8; nt++) {
            unsigned brow = (unsigned)(C0 + 8*nt + (lane & 7));
            unsigned bbase = brow*144 + (lane >> 3)*16;
            #pragma unroll
            for (int kp = 0; kp < 2; kp++) {
                uint32_t bhv[4], blv[4];
                ldsm4(kbh + bbase + kp*64, bhv);
                ldsm4(kbl + bbase + kp*64, blv);
                #pragma unroll
                for (int j = 0; j < 2; j++) {
                    int ks = kp*2 + j;
                    uint32_t bhj[2] = {bhv[2*j], bhv[2*j+1]};
                    uint32_t blj[2] = {blv[2*j], blv[2*j+1]};
                    mmabf(acc[nt], qh[ks], bhj);
                    mmabf(acc[nt], qh[ks], blj);
                    mmabf(acc[nt], ql[ks], bhj);
                }
            }
        }
        float mc1 = -1e30f, mc2 = -1e30f;
        #pragma unroll
        for (int nt = 0; nt < 8; nt++)
            #pragma unroll
            for (int e = 0; e < 2; e++) {
                int gc = ch*128 + C0 + 8*nt + 2*tg + e;
                float u = pkF[gc], u2 = pk2F[gc];
                mc1 = fmaxf(mc1, acc[nt][e]   + a1r*u + u2);
                mc2 = fmaxf(mc2, acc[nt][2+e] + a2r*u + u2);
            }
        float mn1 = fmaxf(m1, mc1 + b1r), mn2 = fmaxf(m2, mc2 + b2r);
        float ac1 = 0.f, ac2 = 0.f;
        #pragma unroll
        for (int nt = 0; nt < 8; nt++)
            #pragma unroll
            for (int e = 0; e < 2; e++) {
                int gc = ch*128 + C0 + 8*nt + 2*tg + e;
                float u = pkF[gc], u2 = pk2F[gc];
                ac1 += __expf(acc[nt][e]   + a1r*u + u2 + b1r - mn1);
                ac2 += __expf(acc[nt][2+e] + a2r*u + u2 + b2r - mn2);
            }
        s1 = s1*__expf(m1 - mn1) + ac1; m1 = mn1;
        s2 = s2*__expf(m2 - mn2) + ac2; m2 = mn2;
        __syncthreads();
    }
    // reduce across tg lanes, then across column halves
    #pragma unroll
    for (int off = 1; off <= 2; off <<= 1) {
        float mo = __shfl_xor_sync(0xffffffffu, m1, off);
        float so = __shfl_xor_sync(0xffffffffu, s1, off);
        float mm = fmaxf(m1, mo);
        s1 = s1*__expf(m1 - mm) + so*__expf(mo - mm); m1 = mm;
        mo = __shfl_xor_sync(0xffffffffu, m2, off);
        so = __shfl_xor_sync(0xffffffffu, s2, off);
        mm = fmaxf(m2, mo);
        s2 = s2*__expf(m2 - mm) + so*__expf(mo - mm); m2 = mm;
    }
    if (tg == 0) {
        redM[chalf*128 + r1] = m1; redS[chalf*128 + r1] = s1;
        redM[chalf*128 + r2] = m2; redS[chalf*128 + r2] = s2;
    }
    __syncthreads();
    if (t < 128) {
        float ma = redM[t], mb = redM[128 + t];
        float sa = redS[t], sbv = redS[128 + t];
        float mm = fmaxf(ma, mb);
        float ss = sa*__expf(ma - mm) + sbv*__expf(mb - mm);
        mS[t] = mm; invS[t] = 1.f/ss;
    }
    __syncthreads();

    const float i1 = invS[r1], i2 = invS[r2];
    const float c1r = b1r - mS[r1], c2r = b2r - mS[r2];   // fold -m into row const

    // ================= PASS 2: attn weights + P@V (register P) ================
    float o[8][4] = {};
    prefetch_k(0, 0); prefetch_v(0, 0); CP_COMMIT();
    for (int ch = 0; ch < NCH; ch++) {
        if (ch + 1 < NCH) {
            prefetch_k(ch+1, (ch+1)&1); prefetch_v(ch+1, (ch+1)&1);
            CP_COMMIT(); CP_WAIT(1);
        } else CP_WAIT(0);
        __syncthreads();
        const unsigned kbh = sb + AT_K(ch & 1, 0), kbl = sb + AT_K(ch & 1, 1);
        const unsigned vbh = sb + AT_V(ch & 1, 0), vbl = sb + AT_V(ch & 1, 1);

        #pragma unroll
        for (int half = 0; half < 2; half++) {
            // --- QK scores for nt in [4*half, 4*half+4) ---
            float acc[4][4] = {};
            #pragma unroll
            for (int nt4 = 0; nt4 < 4; nt4++) {
                int nt = 4*half + nt4;
                unsigned brow = (unsigned)(C0 + 8*nt + (lane & 7));
                unsigned bbase = brow*144 + (lane >> 3)*16;
                #pragma unroll
                for (int kp = 0; kp < 2; kp++) {
                    uint32_t bhv[4], blv[4];
                    ldsm4(kbh + bbase + kp*64, bhv);
                    ldsm4(kbl + bbase + kp*64, blv);
                    #pragma unroll
                    for (int j = 0; j < 2; j++) {
                        int ks = kp*2 + j;
                        uint32_t bhj[2] = {bhv[2*j], bhv[2*j+1]};
                        uint32_t blj[2] = {blv[2*j], blv[2*j+1]};
                        mmabf(acc[nt4], qh[ks], bhj);
                        mmabf(acc[nt4], qh[ks], blj);
                        mmabf(acc[nt4], ql[ks], bhj);
                    }
                }
            }
            // --- exp -> attn write + P A-fragments in registers ---
            uint32_t pAh[2][4], pAl[2][4];      // [local kstep][a-reg]
            #pragma unroll
            for (int nt4 = 0; nt4 < 4; nt4++) {
                int nt = 4*half + nt4;
                int c0 = C0 + 8*nt + 2*tg;
                int gc = ch*128 + c0;
                float u0 = pkF[gc], u20 = pk2F[gc];
                float u1 = pkF[gc+1], u21 = pk2F[gc+1];
                float p10 = __expf(acc[nt4][0] + a1r*u0 + u20 + c1r)*i1;
                float p11 = __expf(acc[nt4][1] + a1r*u1 + u21 + c1r)*i1;
                float p20 = __expf(acc[nt4][2] + a2r*u0 + u20 + c2r)*i2;
                float p21 = __expf(acc[nt4][3] + a2r*u1 + u21 + c2r)*i2;
                float2 w1; w1.x = p10; w1.y = p11;
                float2 w2; w2.x = p20; w2.y = p21;
                *(float2*)(attn_out + ((size_t)bh*SEQ + (size_t)qt*128 + r1)*SEQ + gc) = w1;
                *(float2*)(attn_out + ((size_t)bh*SEQ + (size_t)qt*128 + r2)*SEQ + gc) = w2;
                int kl_ = nt4 >> 1, pos = (nt4 & 1)*2;
                pAh[kl_][pos+0] = pack_hl_hi(p10, p11);
                pAh[kl_][pos+1] = pack_hl_hi(p20, p21);
                pAl[kl_][pos+0] = pack_hl_lo(p10, p11);
                pAl[kl_][pos+1] = pack_hl_lo(p20, p21);
            }
            // --- P @ V for this 32-key group ---
            #pragma unroll
            for (int nt = 0; nt < 8; nt++) {
                unsigned brow = (unsigned)(8*nt + (lane & 7));
                unsigned boff = brow*272 + (unsigned)C0*2 + (unsigned)half*64 + (lane >> 3)*16;
                uint32_t bvh[4], bvl[4];
                ldsm4(vbh + boff, bvh);
                ldsm4(vbl + boff, bvl);
                #pragma unroll
                for (int j = 0; j < 2; j++) {
                    uint32_t bhj[2] = {bvh[2*j], bvh[2*j+1]};
                    uint32_t blj[2] = {bvl[2*j], bvl[2*j+1]};
                    mmabf(o[nt], pAh[j], bhj);
                    mmabf(o[nt], pAh[j], blj);
                    mmabf(o[nt], pAl[j], bhj);
                }
            }
        }
        __syncthreads();
    }

    // ---- merge column halves and write ctx bf16 hi/lo ----
    float* part = (float*)(smc + AT_OPART);     // [128][64]
    if (chalf == 1) {
        #pragma unroll
        for (int nt = 0; nt < 8; nt++) {
            float2 a; a.x = o[nt][0]; a.y = o[nt][1];
            float2 c; c.x = o[nt][2]; c.y = o[nt][3];
            *(float2*)&part[r1*64 + 8*nt + 2*tg] = a;
            *(float2*)&part[r2*64 + 8*nt + 2*tg] = c;
        }
    }
    __syncthreads();
    if (chalf == 0) {
        #pragma unroll
        for (int nt = 0; nt < 8; nt++) {
            int c = 8*nt + 2*tg;
            float2 q1 = *(const float2*)&part[r1*64 + c];
            float2 q2 = *(const float2*)&part[r2*64 + c];
            float v10 = o[nt][0] + q1.x, v11 = o[nt][1] + q1.y;
            float v20 = o[nt][2] + q2.x, v21 = o[nt][3] + q2.y;
            __nv_bfloat16 h0, l0, h1_, l1_;
            size_t idx1 = ((size_t)b*SEQ + (size_t)qt*128 + r1)*DM + h*DH + c;
            size_t idx2 = ((size_t)b*SEQ + (size_t)qt*128 + r2)*DM + h*DH + c;
            __nv_bfloat162 hv, lv;
            split_hl(v10, h0, l0); split_hl(v11, h1_, l1_);
            hv.x = h0; hv.y = h1_; lv.x = l0; lv.y = l1_;
            *(__nv_bfloat162*)(g_ctxh + idx1) = hv;
            *(__nv_bfloat162*)(g_ctxl + idx1) = lv;
            split_hl(v20, h0, l0); split_hl(v21, h1_, l1_);
            hv.x = h0; hv.y = h1_; lv.x = l0; lv.y = l1_;
            *(__nv_bfloat162*)(g_ctxh + idx2) = hv;
            *(__nv_bfloat162*)(g_ctxl + idx2) = lv;
        }
    }
}

// ---------------- launch ------------------------------------------------------
extern "C" void kernel_launch(void* const* d_in, const int* in_sizes, int n_in,
                              void* d_out, int out_size)
{
    const float* x       = (const float*)d_in[0];
    const float* qkv_w   = (const float*)d_in[1];
    const float* qkv_b   = (const float*)d_in[2];
    const float* out_w   = (const float*)d_in[3];
    const float* out_b   = (const float*)d_in[4];
    const float* phase_w = (const float*)d_in[5];
    const float* phase_b = (const float*)d_in[6];
    const float* rscale  = (const float*)d_in[7];
    const float* pscale  = (const float*)d_in[8];

    float* out  = (float*)d_out;                       // [B,L,D]
    float* attn = out + (size_t)NB*SEQ*DM;             // [B,H,L,L]

    __nv_bfloat16 *d_xh, *d_xl, *d_wqh, *d_wql, *d_woh, *d_wol, *d_ctxh, *d_ctxl;
    cudaGetSymbolAddress((void**)&d_xh,  g_xh);
    cudaGetSymbolAddress((void**)&d_xl,  g_xl);
    cudaGetSymbolAddress((void**)&d_wqh, g_wqh);
    cudaGetSymbolAddress((void**)&d_wql, g_wql);
    cudaGetSymbolAddress((void**)&d_woh, g_woh);
    cudaGetSymbolAddress((void**)&d_wol, g_wol);
    cudaGetSymbolAddress((void**)&d_ctxh, g_ctxh);
    cudaGetSymbolAddress((void**)&d_ctxl, g_ctxl);

    cudaFuncSetAttribute(gemm_kernel<0>, cudaFuncAttributeMaxDynamicSharedMemorySize, GEMM_SMEM);
    cudaFuncSetAttribute(gemm_kernel<1>, cudaFuncAttributeMaxDynamicSharedMemorySize, GEMM_SMEM);
    cudaFuncSetAttribute(attn_kernel, cudaFuncAttributeMaxDynamicSharedMemorySize, ATTN_SMEM);

    cvt_kernel<<<512, 256>>>(x,     d_xh,  d_xl,  MTOT*DM);
    cvt_kernel<<<512, 256>>>(qkv_w, d_wqh, d_wql, 3*DM*DM);
    cvt_kernel<<<512, 256>>>(out_w, d_woh, d_wol, DM*DM);

    gemm_kernel<1><<<dim3(3*DM/128, MTOT/128), 512, GEMM_SMEM>>>(
        d_xh, d_xl, d_wqh, d_wql, qkv_b, nullptr);
    phase_kernel<<<dim3(NB*SEQ), 128>>>(x, phase_w, phase_b, pscale);
    attn_kernel<<<dim3(SEQ/128, NH, NB), 512, ATTN_SMEM>>>(attn, rscale);

    gemm_kernel<0><<<dim3(DM/128, MTOT/128), 512, GEMM_SMEM>>>(
        d_ctxh, d_ctxl, d_woh, d_wol, out_b, out);
}

// round 10
// speedup vs baseline: 3.5256x; 1.1066x over previous
#include <cuda_runtime.h>
#include <cuda_bf16.h>
#include <math.h>
#include <stdint.h>

#define NB  2
#define SEQ 2048
#define DM  1024
#define NH  16
#define DH  64
#define MTOT (NB*SEQ)   // 4096
#define NCH (SEQ/128)   // 16

// ---------------- scratch (device globals; no allocation allowed) -------------
__device__ __nv_bfloat16 g_xh [(size_t)MTOT*DM],  g_xl [(size_t)MTOT*DM];
__device__ __nv_bfloat16 g_wqh[(size_t)3*DM*DM],  g_wql[(size_t)3*DM*DM];
__device__ __nv_bfloat16 g_woh[(size_t)DM*DM],    g_wol[(size_t)DM*DM];
__device__ __nv_bfloat16 g_qh [(size_t)NB*NH*SEQ*DH], g_ql[(size_t)NB*NH*SEQ*DH];
__device__ __nv_bfloat16 g_kh [(size_t)NB*NH*SEQ*DH], g_kl[(size_t)NB*NH*SEQ*DH];
__device__ __nv_bfloat16 g_vth[(size_t)NB*NH*DH*SEQ], g_vtl[(size_t)NB*NH*DH*SEQ];
__device__ __nv_bfloat16 g_ctxh[(size_t)MTOT*DM], g_ctxl[(size_t)MTOT*DM];
__device__ float g_pv[(size_t)NB*NH*SEQ];

// ======================= helpers ==============================================
__device__ __forceinline__ unsigned smem_u32(const void* p) {
    unsigned a;
    asm("{ .reg .u64 t; cvta.to.shared.u64 t, %1; cvt.u32.u64 %0, t; }" : "=r"(a) : "l"(p));
    return a;
}
__device__ __forceinline__ void ldsm4(unsigned addr, uint32_t r[4]) {
    asm volatile("ldmatrix.sync.aligned.m8n8.x4.shared.b16 {%0,%1,%2,%3}, [%4];"
        : "=r"(r[0]), "=r"(r[1]), "=r"(r[2]), "=r"(r[3]) : "r"(addr));
}
__device__ __forceinline__ void mmabf(float d[4], const uint32_t a[4], const uint32_t b[2]) {
    asm volatile("mma.sync.aligned.m16n8k16.row.col.f32.bf16.bf16.f32 "
        "{%0,%1,%2,%3},{%4,%5,%6,%7},{%8,%9},{%0,%1,%2,%3};"
        : "+f"(d[0]), "+f"(d[1]), "+f"(d[2]), "+f"(d[3])
        : "r"(a[0]), "r"(a[1]), "r"(a[2]), "r"(a[3]), "r"(b[0]), "r"(b[1]));
}
__device__ __forceinline__ void split_hl(float v, __nv_bfloat16& h, __nv_bfloat16& l) {
    h = __float2bfloat16(v);
    l = __float2bfloat16(v - __bfloat162float(h));
}
__device__ __forceinline__ uint32_t pack_hl_hi(float a, float b) {
    __nv_bfloat162 hv; hv.x = __float2bfloat16(a); hv.y = __float2bfloat16(b);
    return *(uint32_t*)&hv;
}
__device__ __forceinline__ uint32_t pack_hl_lo(float a, float b) {
    __nv_bfloat16 ha = __float2bfloat16(a), hb = __float2bfloat16(b);
    __nv_bfloat162 lv;
    lv.x = __float2bfloat16(a - __bfloat162float(ha));
    lv.y = __float2bfloat16(b - __bfloat162float(hb));
    return *(uint32_t*)&lv;
}
__device__ __forceinline__ void cp16(unsigned saddr, const void* gaddr) {
    asm volatile("cp.async.cg.shared.global [%0], [%1], 16;" :: "r"(saddr), "l"(gaddr));
}
#define CP_COMMIT() asm volatile("cp.async.commit_group;" ::: "memory")
#define CP_WAIT(n)  asm volatile("cp.async.wait_group %0;" :: "n"(n) : "memory")

// ---------------- fp32 -> bf16 hi/lo conversion -------------------------------
__global__ void __launch_bounds__(256) cvt_kernel(const float* __restrict__ in,
                                                  __nv_bfloat16* __restrict__ oh,
                                                  __nv_bfloat16* __restrict__ ol, int n)
{
    for (int i = blockIdx.x*256 + threadIdx.x; i < n; i += gridDim.x*256) {
        __nv_bfloat16 h, l;
        split_hl(in[i], h, l);
        oh[i] = h; ol[i] = l;
    }
}

// ---------------- generic bf16x3 GEMM: C = A @ B^T + bias ---------------------
// 256 threads, tile 128(M) x 64(N), BK=32, 3-stage cp.async, 2 CTAs/SM.
#define GS_AH 0u
#define GS_AL 10240u
#define GS_BH 20480u
#define GS_BL 25600u
#define GS_STAGE 30720u
#define GEMM_SMEM (3u*GS_STAGE)

template <int MODE>
__global__ void __launch_bounds__(256, 2) gemm_kernel(const __nv_bfloat16* __restrict__ Ah,
                                                      const __nv_bfloat16* __restrict__ Al,
                                                      const __nv_bfloat16* __restrict__ Bh,
                                                      const __nv_bfloat16* __restrict__ Bl,
                                                      const float* __restrict__ bias,
                                                      float* __restrict__ Cout)
{
    extern __shared__ char smc[];
    const unsigned sb = smem_u32(smc);
    const int t = threadIdx.x, lane = t & 31, w = t >> 5;
    const int warpm = w >> 1, warpn = w & 1;
    const int blockM = blockIdx.y * 128, blockN = blockIdx.x * 64;
    const int gq = lane >> 2, tg = lane & 3;

    const int prow = t >> 2;                     // 0..63
    const int pcol = (t & 3) << 3;               // bf16 col (8 per 16B)
    const unsigned pso = (unsigned)(prow*80 + (t & 3)*16);

    float acc[2][4][4] = {};

    auto prefetch = [&](int kt, int s) {
        unsigned st = sb + (unsigned)s*GS_STAGE;
        int k0 = kt*32;
        #pragma unroll
        for (int p = 0; p < 2; p++) {
            int row = prow + p*64;
            size_t ga = (size_t)(blockM + row)*DM + k0 + pcol;
            cp16(st + GS_AH + pso + (unsigned)p*64*80, Ah + ga);
            cp16(st + GS_AL + pso + (unsigned)p*64*80, Al + ga);
        }
        size_t gb = (size_t)(blockN + prow)*DM + k0 + pcol;
        cp16(st + GS_BH + pso, Bh + gb);
        cp16(st + GS_BL + pso, Bl + gb);
    };

    prefetch(0, 0); CP_COMMIT();
    prefetch(1, 1); CP_COMMIT();

    for (int kt = 0; kt < 32; kt++) {
        if (kt + 2 < 32) { prefetch(kt+2, (kt+2)%3); CP_COMMIT(); CP_WAIT(2); }
        else CP_WAIT(0);
        __syncthreads();
        const unsigned st = sb + (unsigned)(kt % 3)*GS_STAGE;

        // B fragments for the whole k-tile (k=32 = both ksteps)
        uint32_t bhv[4][4], blv[4][4];
        #pragma unroll
        for (int nt = 0; nt < 4; nt++) {
            unsigned brow = (unsigned)(warpn*32 + nt*8 + (lane & 7));
            unsigned boff = brow*80 + (lane >> 3)*16;
            ldsm4(st + GS_BH + boff, bhv[nt]);
            ldsm4(st + GS_BL + boff, blv[nt]);
        }
        #pragma unroll
        for (int ks = 0; ks < 2; ks++) {
            uint32_t ah[2][4], al[2][4];
            #pragma unroll
            for (int mt = 0; mt < 2; mt++) {
                unsigned arow = (unsigned)(warpm*32 + mt*16 + (lane & 15));
                unsigned aoff = arow*80 + ks*32 + (lane >> 4)*16;
                ldsm4(st + GS_AH + aoff, ah[mt]);
                ldsm4(st + GS_AL + aoff, al[mt]);
            }
            #pragma unroll
            for (int nt = 0; nt < 4; nt++) {
                uint32_t bhj[2] = {bhv[nt][2*ks], bhv[nt][2*ks+1]};
                uint32_t blj[2] = {blv[nt][2*ks], blv[nt][2*ks+1]};
                #pragma unroll
                for (int mt = 0; mt < 2; mt++) {
                    mmabf(acc[mt][nt], ah[mt], bhj);
                    mmabf(acc[mt][nt], ah[mt], blj);
                    mmabf(acc[mt][nt], al[mt], bhj);
                }
            }
        }
        __syncthreads();
    }

    // epilogue
    #pragma unroll
    for (int mt = 0; mt < 2; mt++) {
        #pragma unroll
        for (int nt = 0; nt < 4; nt++) {
            int n  = blockN + warpn*32 + nt*8 + 2*tg;
            float b0 = bias[n], b1 = bias[n+1];
            int m0 = blockM + warpm*32 + mt*16 + gq;
            float v[2][2] = {{acc[mt][nt][0] + b0, acc[mt][nt][1] + b1},
                             {acc[mt][nt][2] + b0, acc[mt][nt][3] + b1}};
            #pragma unroll
            for (int r = 0; r < 2; r++) {
                int m = m0 + r*8;
                if (MODE == 0) {
                    float2 o; o.x = v[r][0]; o.y = v[r][1];
                    *(float2*)(Cout + (size_t)m*DM + n) = o;
                } else {
                    int which = n >> 10, hd = n & 1023;
                    int hh = hd >> 6, d = hd & 63;
                    int bb = m >> 11, l = m & (SEQ-1);
                    int bhid = bb*NH + hh;
                    float v0 = v[r][0], v1 = v[r][1];
                    if (which == 0) { v0 *= 0.125f; v1 *= 0.125f; }
                    __nv_bfloat16 h0, l0, h1, l1;
                    split_hl(v0, h0, l0); split_hl(v1, h1, l1);
                    if (which == 2) {
                        size_t base = ((size_t)bhid*DH + d)*SEQ + l;
                        g_vth[base] = h0; g_vth[base + SEQ] = h1;
                        g_vtl[base] = l0; g_vtl[base + SEQ] = l1;
                    } else {
                        size_t idx = ((size_t)bhid*SEQ + l)*DH + d;
                        __nv_bfloat16* H = which ? g_kh : g_qh;
                        __nv_bfloat16* L = which ? g_kl : g_ql;
                        __nv_bfloat162 hv; hv.x = h0; hv.y = h1;
                        __nv_bfloat162 lv; lv.x = l0; lv.y = l1;
                        *(__nv_bfloat162*)(H + idx) = hv;
                        *(__nv_bfloat162*)(L + idx) = lv;
                    }
                }
            }
        }
    }
}

// ---------------- phase projection --------------------------------------------
__global__ void __launch_bounds__(128) phase_kernel(const float* __restrict__ X,
                                                    const float* __restrict__ PW,
                                                    const float* __restrict__ PB,
                                                    const float* __restrict__ pscale)
{
    __shared__ float xs[DM];
    const int row = blockIdx.x;            // b*L + l
    for (int i = threadIdx.x; i < DM; i += 128) xs[i] = X[(size_t)row*DM + i];
    __syncthreads();
    const int h  = threadIdx.x >> 3;
    const int ln = threadIdx.x & 7;
    float s = 0.f;
    for (int k = ln; k < DM; k += 8) s += xs[k]*PW[(size_t)h*DM + k];
    #pragma unroll
    for (int off = 4; off; off >>= 1) s += __shfl_xor_sync(0xffffffffu, s, off);
    if (ln == 0) {
        float v = tanhf(pscale[0]*(s + PB[h]));
        int b = row >> 11, l = row & (SEQ-1);
        g_pv[((size_t)(b*NH + h))*SEQ + l] = v;
    }
}

// ---------------- fused attention (mma.sync, 2-pass, register P) --------------
// Pass 1 uses single bf16 MMA (hi only) — sum/max tolerance allows it.
#define AT_Q(hl)    (18432u*(unsigned)(hl))
#define AT_K(s,hl)  (36864u  + 18432u*(unsigned)((s)*2+(hl)))
#define AT_V(s,hl)  (110592u + 17408u*(unsigned)((s)*2+(hl)))
#define AT_PK    180224u
#define AT_PK2   188416u
#define AT_PQ    196608u
#define AT_MS    197120u
#define AT_INV   197632u
#define AT_RED   198144u
#define AT_OPART 36864u          /* reuse K buffers post-loop */
#define ATTN_SMEM 200192u

__global__ void __launch_bounds__(512) attn_kernel(float* __restrict__ attn_out,
                                                   const float* __restrict__ rscale_p)
{
    extern __shared__ char smc[];
    const unsigned sb = smem_u32(smc);
    const int t = threadIdx.x, lane = t & 31, w = t >> 5;
    const int R0 = (w >> 1)*16;
    const int chalf = w & 1, C0 = chalf*64;
    const int gq = lane >> 2, tg = lane & 3;
    const int r1 = R0 + gq, r2 = r1 + 8;

    const int qt = blockIdx.x, h = blockIdx.y, b = blockIdx.z;
    const int bh = b*NH + h;
    const float rs = rscale_p[0];

    const __nv_bfloat16* Qh  = g_qh  + ((size_t)bh*SEQ + (size_t)qt*128)*DH;
    const __nv_bfloat16* Ql  = g_ql  + ((size_t)bh*SEQ + (size_t)qt*128)*DH;
    const __nv_bfloat16* Kh  = g_kh  + (size_t)bh*SEQ*DH;
    const __nv_bfloat16* Kl  = g_kl  + (size_t)bh*SEQ*DH;
    const __nv_bfloat16* VTh = g_vth + (size_t)bh*DH*SEQ;
    const __nv_bfloat16* VTl = g_vtl + (size_t)bh*DH*SEQ;
    const float*         PV  = g_pv  + (size_t)bh*SEQ;

    float* pkF  = (float*)(smc + AT_PK);
    float* pk2F = (float*)(smc + AT_PK2);
    float* pqF  = (float*)(smc + AT_PQ);
    float* mS   = (float*)(smc + AT_MS);
    float* invS = (float*)(smc + AT_INV);
    float* redM = (float*)(smc + AT_RED);       // [2][128]
    float* redS = redM + 256;                   // [2][128]

    const int krow = t >> 3, kc8 = (t & 7) << 3;
    const unsigned kso = (unsigned)(krow*72 + kc8)*2;
    const int vdh = t >> 4, vc8 = (t & 15) << 3;
    const unsigned vso = (unsigned)(vdh*136 + vc8)*2;

    auto prefetch_k_hi = [&](int ch, int s) {    // pass-1: hi only
        const __nv_bfloat16* kh = Kh + (size_t)ch*128*DH;
        #pragma unroll
        for (int p = 0; p < 2; p++) {
            int row = krow + p*64;
            cp16(sb + AT_K(s,0) + kso + (unsigned)p*64*144, kh + row*DH + kc8);
        }
    };
    auto prefetch_k = [&](int ch, int s) {
        const __nv_bfloat16* kh = Kh + (size_t)ch*128*DH;
        const __nv_bfloat16* kl = Kl + (size_t)ch*128*DH;
        #pragma unroll
        for (int p = 0; p < 2; p++) {
            int row = krow + p*64;
            unsigned so = kso + (unsigned)p*64*144;
            cp16(sb + AT_K(s,0) + so, kh + row*DH + kc8);
            cp16(sb + AT_K(s,1) + so, kl + row*DH + kc8);
        }
    };
    auto prefetch_v = [&](int ch, int s) {
        #pragma unroll
        for (int p = 0; p < 2; p++) {
            int dh = vdh + p*32;
            unsigned so = vso + (unsigned)p*32*272;
            cp16(sb + AT_V(s,0) + so, VTh + (size_t)dh*SEQ + ch*128 + vc8);
            cp16(sb + AT_V(s,1) + so, VTl + (size_t)dh*SEQ + ch*128 + vc8);
        }
    };

    // stage Q (hi/lo) + phase values
    prefetch_k_hi(0, 0); CP_COMMIT();
    #pragma unroll
    for (int p = 0; p < 2; p++) {
        int i = t + p*512;
        int row = i >> 3, c8 = (i & 7) << 3;
        unsigned so = (unsigned)(row*72 + c8)*2;
        *(uint4*)(smc + AT_Q(0) + so) = *(const uint4*)(Qh + row*DH + c8);
        *(uint4*)(smc + AT_Q(1) + so) = *(const uint4*)(Ql + row*DH + c8);
    }
    for (int i = t; i < SEQ; i += 512) {
        float pv = PV[i];
        pkF[i] = pv; pk2F[i] = -rs*pv*pv;
    }
    if (t < 128) pqF[t] = PV[qt*128 + t];
    __syncthreads();

    // Q fragments (held in registers across both passes)
    uint32_t qh[4][4], ql[4][4];
    #pragma unroll
    for (int ks = 0; ks < 4; ks++) {
        unsigned arow = R0 + (lane & 15);
        unsigned aoff = arow*144 + ks*32 + (lane >> 4)*16;
        ldsm4(sb + AT_Q(0) + aoff, qh[ks]);
        ldsm4(sb + AT_Q(1) + aoff, ql[ks]);
    }

    const float pq1v = pqF[r1], pq2v = pqF[r2];
    const float a1r = 2.f*rs*pq1v, b1r = -rs*pq1v*pq1v;
    const float a2r = 2.f*rs*pq2v, b2r = -rs*pq2v*pq2v;

    // ================= PASS 1: row max + exp-sum (hi-only MMA) ================
    float m1 = -1e30f, s1 = 0.f, m2 = -1e30f, s2 = 0.f;
    for (int ch = 0; ch < NCH; ch++) {
        if (ch + 1 < NCH) { prefetch_k_hi(ch+1, (ch+1)&1); CP_COMMIT(); CP_WAIT(1); }
        else CP_WAIT(0);
        __syncthreads();
        const unsigned kbh = sb + AT_K(ch & 1, 0);

        float acc[8][4] = {};
        #pragma unroll
        for (int nt = 0; nt < 8; nt++) {
            unsigned brow = (unsigned)(C0 + 8*nt + (lane & 7));
            unsigned bbase = brow*144 + (lane >> 3)*16;
            #pragma unroll
            for (int kp = 0; kp < 2; kp++) {
                uint32_t bhv[4];
                ldsm4(kbh + bbase + kp*64, bhv);
                #pragma unroll
                for (int j = 0; j < 2; j++) {
                    int ks = kp*2 + j;
                    uint32_t bhj[2] = {bhv[2*j], bhv[2*j+1]};
                    mmabf(acc[nt], qh[ks], bhj);
                }
            }
        }
        float mc1 = -1e30f, mc2 = -1e30f;
        #pragma unroll
        for (int nt = 0; nt < 8; nt++)
            #pragma unroll
            for (int e = 0; e < 2; e++) {
                int gc = ch*128 + C0 + 8*nt + 2*tg + e;
                float u = pkF[gc], u2 = pk2F[gc];
                mc1 = fmaxf(mc1, acc[nt][e]   + a1r*u + u2);
                mc2 = fmaxf(mc2, acc[nt][2+e] + a2r*u + u2);
            }
        float mn1 = fmaxf(m1, mc1 + b1r), mn2 = fmaxf(m2, mc2 + b2r);
        float ac1 = 0.f, ac2 = 0.f;
        #pragma unroll
        for (int nt = 0; nt < 8; nt++)
            #pragma unroll
            for (int e = 0; e < 2; e++) {
                int gc = ch*128 + C0 + 8*nt + 2*tg + e;
                float u = pkF[gc], u2 = pk2F[gc];
                ac1 += __expf(acc[nt][e]   + a1r*u + u2 + b1r - mn1);
                ac2 += __expf(acc[nt][2+e] + a2r*u + u2 + b2r - mn2);
            }
        s1 = s1*__expf(m1 - mn1) + ac1; m1 = mn1;
        s2 = s2*__expf(m2 - mn2) + ac2; m2 = mn2;
        __syncthreads();
    }
    // reduce across tg lanes, then across column halves
    #pragma unroll
    for (int off = 1; off <= 2; off <<= 1) {
        float mo = __shfl_xor_sync(0xffffffffu, m1, off);
        float so = __shfl_xor_sync(0xffffffffu, s1, off);
        float mm = fmaxf(m1, mo);
        s1 = s1*__expf(m1 - mm) + so*__expf(mo - mm); m1 = mm;
        mo = __shfl_xor_sync(0xffffffffu, m2, off);
        so = __shfl_xor_sync(0xffffffffu, s2, off);
        mm = fmaxf(m2, mo);
        s2 = s2*__expf(m2 - mm) + so*__expf(mo - mm); m2 = mm;
    }
    if (tg == 0) {
        redM[chalf*128 + r1] = m1; redS[chalf*128 + r1] = s1;
        redM[chalf*128 + r2] = m2; redS[chalf*128 + r2] = s2;
    }
    __syncthreads();
    if (t < 128) {
        float ma = redM[t], mb = redM[128 + t];
        float sa = redS[t], sbv = redS[128 + t];
        float mm = fmaxf(ma, mb);
        float ss = sa*__expf(ma - mm) + sbv*__expf(mb - mm);
        mS[t] = mm; invS[t] = 1.f/ss;
    }
    __syncthreads();

    const float i1 = invS[r1], i2 = invS[r2];
    const float c1r = b1r - mS[r1], c2r = b2r - mS[r2];   // fold -m into row const

    // ================= PASS 2: attn weights + P@V (register P) ================
    float o[8][4] = {};
    prefetch_k(0, 0); prefetch_v(0, 0); CP_COMMIT();
    for (int ch = 0; ch < NCH; ch++) {
        if (ch + 1 < NCH) {
            prefetch_k(ch+1, (ch+1)&1); prefetch_v(ch+1, (ch+1)&1);
            CP_COMMIT(); CP_WAIT(1);
        } else CP_WAIT(0);
        __syncthreads();
        const unsigned kbh = sb + AT_K(ch & 1, 0), kbl = sb + AT_K(ch & 1, 1);
        const unsigned vbh = sb + AT_V(ch & 1, 0), vbl = sb + AT_V(ch & 1, 1);

        #pragma unroll
        for (int half = 0; half < 2; half++) {
            // --- QK scores for nt in [4*half, 4*half+4) ---
            float acc[4][4] = {};
            #pragma unroll
            for (int nt4 = 0; nt4 < 4; nt4++) {
                int nt = 4*half + nt4;
                unsigned brow = (unsigned)(C0 + 8*nt + (lane & 7));
                unsigned bbase = brow*144 + (lane >> 3)*16;
                #pragma unroll
                for (int kp = 0; kp < 2; kp++) {
                    uint32_t bhv[4], blv[4];
                    ldsm4(kbh + bbase + kp*64, bhv);
                    ldsm4(kbl + bbase + kp*64, blv);
                    #pragma unroll
                    for (int j = 0; j < 2; j++) {
                        int ks = kp*2 + j;
                        uint32_t bhj[2] = {bhv[2*j], bhv[2*j+1]};
                        uint32_t blj[2] = {blv[2*j], blv[2*j+1]};
                        mmabf(acc[nt4], qh[ks], bhj);
                        mmabf(acc[nt4], qh[ks], blj);
                        mmabf(acc[nt4], ql[ks], bhj);
                    }
                }
            }
            // --- exp -> attn write + P A-fragments in registers ---
            uint32_t pAh[2][4], pAl[2][4];      // [local kstep][a-reg]
            #pragma unroll
            for (int nt4 = 0; nt4 < 4; nt4++) {
                int nt = 4*half + nt4;
                int c0 = C0 + 8*nt + 2*tg;
                int gc = ch*128 + c0;
                float u0 = pkF[gc], u20 = pk2F[gc];
                float u1 = pkF[gc+1], u21 = pk2F[gc+1];
                float p10 = __expf(acc[nt4][0] + a1r*u0 + u20 + c1r)*i1;
                float p11 = __expf(acc[nt4][1] + a1r*u1 + u21 + c1r)*i1;
                float p20 = __expf(acc[nt4][2] + a2r*u0 + u20 + c2r)*i2;
                float p21 = __expf(acc[nt4][3] + a2r*u1 + u21 + c2r)*i2;
                float2 w1; w1.x = p10; w1.y = p11;
                float2 w2; w2.x = p20; w2.y = p21;
                *(float2*)(attn_out + ((size_t)bh*SEQ + (size_t)qt*128 + r1)*SEQ + gc) = w1;
                *(float2*)(attn_out + ((size_t)bh*SEQ + (size_t)qt*128 + r2)*SEQ + gc) = w2;
                int kl_ = nt4 >> 1, pos = (nt4 & 1)*2;
                pAh[kl_][pos+0] = pack_hl_hi(p10, p11);
                pAh[kl_][pos+1] = pack_hl_hi(p20, p21);
                pAl[kl_][pos+0] = pack_hl_lo(p10, p11);
                pAl[kl_][pos+1] = pack_hl_lo(p20, p21);
            }
            // --- P @ V for this 32-key group ---
            #pragma unroll
            for (int nt = 0; nt < 8; nt++) {
                unsigned brow = (unsigned)(8*nt + (lane & 7));
                unsigned boff = brow*272 + (unsigned)C0*2 + (unsigned)half*64 + (lane >> 3)*16;
                uint32_t bvh[4], bvl[4];
                ldsm4(vbh + boff, bvh);
                ldsm4(vbl + boff, bvl);
                #pragma unroll
                for (int j = 0; j < 2; j++) {
                    uint32_t bhj[2] = {bvh[2*j], bvh[2*j+1]};
                    uint32_t blj[2] = {bvl[2*j], bvl[2*j+1]};
                    mmabf(o[nt], pAh[j], bhj);
                    mmabf(o[nt], pAh[j], blj);
                    mmabf(o[nt], pAl[j], bhj);
                }
            }
        }
        __syncthreads();
    }

    // ---- merge column halves and write ctx bf16 hi/lo ----
    float* part = (float*)(smc + AT_OPART);     // [128][64]
    if (chalf == 1) {
        #pragma unroll
        for (int nt = 0; nt < 8; nt++) {
            float2 a; a.x = o[nt][0]; a.y = o[nt][1];
            float2 c; c.x = o[nt][2]; c.y = o[nt][3];
            *(float2*)&part[r1*64 + 8*nt + 2*tg] = a;
            *(float2*)&part[r2*64 + 8*nt + 2*tg] = c;
        }
    }
    __syncthreads();
    if (chalf == 0) {
        #pragma unroll
        for (int nt = 0; nt < 8; nt++) {
            int c = 8*nt + 2*tg;
            float2 q1 = *(const float2*)&part[r1*64 + c];
            float2 q2 = *(const float2*)&part[r2*64 + c];
            float v10 = o[nt][0] + q1.x, v11 = o[nt][1] + q1.y;
            float v20 = o[nt][2] + q2.x, v21 = o[nt][3] + q2.y;
            __nv_bfloat16 h0, l0, h1_, l1_;
            size_t idx1 = ((size_t)b*SEQ + (size_t)qt*128 + r1)*DM + h*DH + c;
            size_t idx2 = ((size_t)b*SEQ + (size_t)qt*128 + r2)*DM + h*DH + c;
            __nv_bfloat162 hv, lv;
            split_hl(v10, h0, l0); split_hl(v11, h1_, l1_);
            hv.x = h0; hv.y = h1_; lv.x = l0; lv.y = l1_;
            *(__nv_bfloat162*)(g_ctxh + idx1) = hv;
            *(__nv_bfloat162*)(g_ctxl + idx1) = lv;
            split_hl(v20, h0, l0); split_hl(v21, h1_, l1_);
            hv.x = h0; hv.y = h1_; lv.x = l0; lv.y = l1_;
            *(__nv_bfloat162*)(g_ctxh + idx2) = hv;
            *(__nv_bfloat162*)(g_ctxl + idx2) = lv;
        }
    }
}

// ---------------- launch ------------------------------------------------------
extern "C" void kernel_launch(void* const* d_in, const int* in_sizes, int n_in,
                              void* d_out, int out_size)
{
    const float* x       = (const float*)d_in[0];
    const float* qkv_w   = (const float*)d_in[1];
    const float* qkv_b   = (const float*)d_in[2];
    const float* out_w   = (const float*)d_in[3];
    const float* out_b   = (const float*)d_in[4];
    const float* phase_w = (const float*)d_in[5];
    const float* phase_b = (const float*)d_in[6];
    const float* rscale  = (const float*)d_in[7];
    const float* pscale  = (const float*)d_in[8];

    float* out  = (float*)d_out;                       // [B,L,D]
    float* attn = out + (size_t)NB*SEQ*DM;             // [B,H,L,L]

    __nv_bfloat16 *d_xh, *d_xl, *d_wqh, *d_wql, *d_woh, *d_wol, *d_ctxh, *d_ctxl;
    cudaGetSymbolAddress((void**)&d_xh,  g_xh);
    cudaGetSymbolAddress((void**)&d_xl,  g_xl);
    cudaGetSymbolAddress((void**)&d_wqh, g_wqh);
    cudaGetSymbolAddress((void**)&d_wql, g_wql);
    cudaGetSymbolAddress((void**)&d_woh, g_woh);
    cudaGetSymbolAddress((void**)&d_wol, g_wol);
    cudaGetSymbolAddress((void**)&d_ctxh, g_ctxh);
    cudaGetSymbolAddress((void**)&d_ctxl, g_ctxl);

    cudaFuncSetAttribute(gemm_kernel<0>, cudaFuncAttributeMaxDynamicSharedMemorySize, GEMM_SMEM);
    cudaFuncSetAttribute(gemm_kernel<1>, cudaFuncAttributeMaxDynamicSharedMemorySize, GEMM_SMEM);
    cudaFuncSetAttribute(attn_kernel, cudaFuncAttributeMaxDynamicSharedMemorySize, ATTN_SMEM);

    cvt_kernel<<<512, 256>>>(x,     d_xh,  d_xl,  MTOT*DM);
    cvt_kernel<<<512, 256>>>(qkv_w, d_wqh, d_wql, 3*DM*DM);
    cvt_kernel<<<512, 256>>>(out_w, d_woh, d_wol, DM*DM);

    gemm_kernel<1><<<dim3(3*DM/64, MTOT/128), 256, GEMM_SMEM>>>(
        d_xh, d_xl, d_wqh, d_wql, qkv_b, nullptr);
    phase_kernel<<<dim3(NB*SEQ), 128>>>(x, phase_w, phase_b, pscale);
    attn_kernel<<<dim3(SEQ/128, NH, NB), 512, ATTN_SMEM>>>(attn, rscale);

    gemm_kernel<0><<<dim3(DM/64, MTOT/128), 256, GEMM_SMEM>>>(
        d_ctxh, d_ctxl, d_woh, d_wol, out_b, out);
}